// round 11
// baseline (speedup 1.0000x reference)
#include <cuda_runtime.h>
#include <cuda_bf16.h>
#include <math.h>

// Problem constants
#define BATCH   2
#define SEQLEN  2048
#define DMODEL  2048
#define NHEADS  16
#define DHEAD   128
#define MTOT    (BATCH * SEQLEN)      // 4096

typedef unsigned int u32;
typedef unsigned short u16;

// ---- bf16 split helper: v = hi + lo with ~2^-16 combined relative residual
__device__ __forceinline__ void split1(float v, __nv_bfloat16& h, __nv_bfloat16& l) {
    h = __float2bfloat16(v);
    l = __float2bfloat16(v - __bfloat162float(h));
}
__device__ __forceinline__ u32 pack2bf(float lo, float hi) {
    u32 r; asm("cvt.rn.bf16x2.f32 %0, %1, %2;" : "=r"(r) : "f"(hi), "f"(lo)); return r;
}
__device__ __forceinline__ float ex2f(float x) {
    float y; asm("ex2.approx.f32 %0, %1;" : "=f"(y) : "f"(x)); return y;
}
// ---- cp.async helpers (16B)
__device__ __forceinline__ void cpa16(u32 dst_smem, const void* src) {
    asm volatile("cp.async.cg.shared.global [%0], [%1], 16;" :: "r"(dst_smem), "l"(src));
}
#define CP_COMMIT() asm volatile("cp.async.commit_group;")
#define CP_WAIT0()  asm volatile("cp.async.wait_group 0;")

// ---- ldmatrix helpers
__device__ __forceinline__ void ldsm_x4(u32* r, u32 addr) {
    asm volatile("ldmatrix.sync.aligned.m8n8.x4.shared.b16 {%0,%1,%2,%3}, [%4];"
        : "=r"(r[0]), "=r"(r[1]), "=r"(r[2]), "=r"(r[3]) : "r"(addr));
}
__device__ __forceinline__ void ldsm_x4_t(u32* r, u32 addr) {
    asm volatile("ldmatrix.sync.aligned.m8n8.x4.trans.shared.b16 {%0,%1,%2,%3}, [%4];"
        : "=r"(r[0]), "=r"(r[1]), "=r"(r[2]), "=r"(r[3]) : "r"(addr));
}

// ---- scratch (device globals; device-side refs only)
__device__ __nv_bfloat16 gx_hi[(size_t)MTOT * DMODEL];
__device__ __nv_bfloat16 gx_lo[(size_t)MTOT * DMODEL];
__device__ __nv_bfloat16 gq_hi[(size_t)MTOT * DMODEL];
__device__ __nv_bfloat16 gq_lo[(size_t)MTOT * DMODEL];
__device__ __nv_bfloat16 gk_hi[(size_t)MTOT * DMODEL];
__device__ __nv_bfloat16 gk_lo[(size_t)MTOT * DMODEL];
__device__ __nv_bfloat16 gv_hi[(size_t)MTOT * DMODEL];
__device__ __nv_bfloat16 gv_lo[(size_t)MTOT * DMODEL];
__device__ __nv_bfloat16 gz_hi[(size_t)MTOT * DMODEL];
__device__ __nv_bfloat16 gz_lo[(size_t)MTOT * DMODEL];
// QKV weights transposed per head: [which][h][n(128)][k(2048)]
__device__ __nv_bfloat16 gw_hi[(size_t)3 * NHEADS * DHEAD * DMODEL];
__device__ __nv_bfloat16 gw_lo[(size_t)3 * NHEADS * DHEAD * DMODEL];
// W_O transposed: [n(2048)][k(2048)]
__device__ __nv_bfloat16 gwo_hi[(size_t)DMODEL * DMODEL];
__device__ __nv_bfloat16 gwo_lo[(size_t)DMODEL * DMODEL];

// ---------------------------------------------------------------------------
// Prep kernels
// ---------------------------------------------------------------------------
__global__ void __launch_bounds__(256) split_x_kernel(const float* __restrict__ x)
{
    size_t i = (size_t)blockIdx.x * blockDim.x + threadIdx.x;
    float2 v = ((const float2*)x)[i];
    __nv_bfloat16 h0, l0, h1, l1;
    split1(v.x, h0, l0); split1(v.y, h1, l1);
    __nv_bfloat162 hp; hp.x = h0; hp.y = h1;
    __nv_bfloat162 lp; lp.x = l0; lp.y = l1;
    ((__nv_bfloat162*)gx_hi)[i] = hp;
    ((__nv_bfloat162*)gx_lo)[i] = lp;
}

__global__ void split_w_kernel(const float* __restrict__ Wq,
                               const float* __restrict__ Wk,
                               const float* __restrict__ Wv)
{
    const int which = blockIdx.z / NHEADS;
    const int h     = blockIdx.z % NHEADS;
    const float* W = ((which == 0) ? Wq : (which == 1) ? Wk : Wv)
                     + (size_t)h * DMODEL * DHEAD;
    const int k0 = blockIdx.x * 32;
    const int n0 = blockIdx.y * 32;

    __shared__ float tile[32][33];
    const int tx = threadIdx.x, ty = threadIdx.y;
#pragma unroll
    for (int r = 0; r < 4; r++)
        tile[ty + 8 * r][tx] = W[(size_t)(k0 + ty + 8 * r) * DHEAD + n0 + tx];
    __syncthreads();
    const size_t base = ((size_t)(which * NHEADS + h) * DHEAD);
#pragma unroll
    for (int r = 0; r < 4; r++) {
        float v = tile[tx][ty + 8 * r];
        __nv_bfloat16 hh, ll; split1(v, hh, ll);
        size_t idx = (base + n0 + ty + 8 * r) * DMODEL + k0 + tx;
        gw_hi[idx] = hh; gw_lo[idx] = ll;
    }
}

__global__ void split_wo_kernel(const float* __restrict__ Wo)
{
    const int k0 = blockIdx.x * 32;
    const int n0 = blockIdx.y * 32;
    __shared__ float tile[32][33];
    const int tx = threadIdx.x, ty = threadIdx.y;
#pragma unroll
    for (int r = 0; r < 4; r++)
        tile[ty + 8 * r][tx] = Wo[(size_t)(k0 + ty + 8 * r) * DMODEL + n0 + tx];
    __syncthreads();
#pragma unroll
    for (int r = 0; r < 4; r++) {
        float v = tile[tx][ty + 8 * r];
        __nv_bfloat16 hh, ll; split1(v, hh, ll);
        size_t idx = (size_t)(n0 + ty + 8 * r) * DMODEL + k0 + tx;
        gwo_hi[idx] = hh; gwo_lo[idx] = ll;
    }
}

// ---------------------------------------------------------------------------
// bf16 split-GEMM core (mma m16n8k16, 3-term), cp.async 2-stage pipeline,
// ONE __syncthreads per K-iteration, ldmatrix fragment loads.
// Block 256 thr (8 warps, 4x2), tile 128x128, K step 32, 80 KB smem.
// ---------------------------------------------------------------------------
#define KC   32
#define SSTR 40
#define GARR  (128 * SSTR)          // elems per array per stage
#define GSTAGE (4 * GARR)           // elems per stage
#define GEMM_SMEM (2 * GSTAGE * 2)  // 81920 bytes

#define MMA_BF16(c, a, b) \
    asm volatile("mma.sync.aligned.m16n8k16.row.col.f32.bf16.bf16.f32 " \
        "{%0,%1,%2,%3}, {%4,%5,%6,%7}, {%8,%9}, {%0,%1,%2,%3};" \
        : "+f"((c)[0]), "+f"((c)[1]), "+f"((c)[2]), "+f"((c)[3]) \
        : "r"((a)[0]), "r"((a)[1]), "r"((a)[2]), "r"((a)[3]), \
          "r"((b)[0]), "r"((b)[1]))

__device__ __forceinline__ void gemm_split_core(
    const __nv_bfloat16* __restrict__ Ah, const __nv_bfloat16* __restrict__ Al,
    const __nv_bfloat16* __restrict__ Bh, const __nv_bfloat16* __restrict__ Bl,
    int mBase, float acc[2][8][4], __nv_bfloat16* smem)
{
    const int tid  = threadIdx.x;
    const int wid  = tid >> 5;
    const int lane = tid & 31;
    const int wm = (wid & 3) * 32;
    const int wn = (wid >> 2) * 64;

    // ldmatrix lane geometry
    const int lr  = lane & 15;
    const int kof = 8 * (lane >> 4);

    const u32 sbase = (u32)__cvta_generic_to_shared(smem);

#pragma unroll
    for (int am = 0; am < 2; am++)
#pragma unroll
        for (int an = 0; an < 8; an++)
#pragma unroll
            for (int c = 0; c < 4; c++) acc[am][an][c] = 0.f;

    // issue one K-tile (4 arrays x 128 rows x 32 bf16 = 512 x 16B chunks each)
    auto issue_tile = [&](int k0, int st) {
        const u32 b0 = sbase + (u32)st * (GSTAGE * 2);
#pragma unroll
        for (int it = 0; it < 2; it++) {
            const int idx = tid + it * 256;      // 0..511
            const int r = idx >> 2;
            const int c = idx & 3;
            const u32 doff = (u32)(r * SSTR + c * 8) * 2;
            const size_t aoff = (size_t)(mBase + r) * DMODEL + k0 + c * 8;
            const size_t boff = (size_t)r * DMODEL + k0 + c * 8;
            cpa16(b0 + doff,                 Ah + aoff);
            cpa16(b0 + GARR * 2 + doff,      Al + aoff);
            cpa16(b0 + 2 * GARR * 2 + doff,  Bh + boff);
            cpa16(b0 + 3 * GARR * 2 + doff,  Bl + boff);
        }
        CP_COMMIT();
    };

    const int NKT = DMODEL / KC;   // 64
    issue_tile(0, 0);

    for (int kt = 0; kt < NKT; kt++) {
        const int cur = kt & 1;
        CP_WAIT0();        // tile kt landed (only group outstanding)
        __syncthreads();   // tile kt visible to all; compute(kt-1) on 1-cur done
        if (kt + 1 < NKT) issue_tile((kt + 1) * KC, 1 - cur);

        const u32 b0 = sbase + (u32)cur * (GSTAGE * 2);
        const u32 aH = b0;
        const u32 aL = b0 + GARR * 2;
        const u32 bH = b0 + 2 * GARR * 2;
        const u32 bL = b0 + 3 * GARR * 2;

#pragma unroll
        for (int ks = 0; ks < KC; ks += 16) {
            u32 afh[2][4], afl[2][4];
#pragma unroll
            for (int am = 0; am < 2; am++) {
                const u32 off = (u32)(((wm + am * 16 + lr) * SSTR + ks + kof) * 2);
                ldsm_x4(afh[am], aH + off);
                ldsm_x4(afl[am], aL + off);
            }
            u32 bfh[8][2], bfl[8][2];
#pragma unroll
            for (int p = 0; p < 4; p++) {
                const u32 off = (u32)(((wn + p * 16 + lr) * SSTR + ks + kof) * 2);
                u32 r[4];
                ldsm_x4(r, bH + off);
                bfh[2 * p][0] = r[0]; bfh[2 * p + 1][0] = r[1];
                bfh[2 * p][1] = r[2]; bfh[2 * p + 1][1] = r[3];
                ldsm_x4(r, bL + off);
                bfl[2 * p][0] = r[0]; bfl[2 * p + 1][0] = r[1];
                bfl[2 * p][1] = r[2]; bfl[2 * p + 1][1] = r[3];
            }
#pragma unroll
            for (int am = 0; am < 2; am++)
#pragma unroll
                for (int an = 0; an < 8; an++) {
                    MMA_BF16(acc[am][an], afh[am], bfh[an]);
                    MMA_BF16(acc[am][an], afh[am], bfl[an]);
                    MMA_BF16(acc[am][an], afl[am], bfh[an]);
                }
        }
    }
}

// QKV: grid (M/128, NHEADS, 3), block 256. Writes split q/k/v in [b,h,s,d].
__global__ void __launch_bounds__(256) qkv_mma_kernel(
    const float* __restrict__ bQ, const float* __restrict__ bK, const float* __restrict__ bV)
{
    extern __shared__ __nv_bfloat16 smem[];
    const int mBase = blockIdx.x * 128;
    const int h     = blockIdx.y;
    const int which = blockIdx.z;
    const float* bias = ((which == 0) ? bQ : (which == 1) ? bK : bV) + h * DHEAD;
    __nv_bfloat16* dhi = (which == 0) ? gq_hi : (which == 1) ? gk_hi : gv_hi;
    __nv_bfloat16* dlo = (which == 0) ? gq_lo : (which == 1) ? gk_lo : gv_lo;
    const __nv_bfloat16* Bh = gw_hi + (size_t)(which * NHEADS + h) * DHEAD * DMODEL;
    const __nv_bfloat16* Bl = gw_lo + (size_t)(which * NHEADS + h) * DHEAD * DMODEL;

    float acc[2][8][4];
    gemm_split_core(gx_hi, gx_lo, Bh, Bl, mBase, acc, smem);

    const int tid = threadIdx.x, wid = tid >> 5, lane = tid & 31;
    const int wm = (wid & 3) * 32, wn = (wid >> 2) * 64;
    const int g = lane >> 2, t = lane & 3;

#pragma unroll
    for (int am = 0; am < 2; am++)
#pragma unroll
        for (int an = 0; an < 8; an++) {
            const int col = wn + an * 8 + 2 * t;
            const float b0 = bias[col], b1 = bias[col + 1];
#pragma unroll
            for (int half = 0; half < 2; half++) {
                const int m = mBase + wm + am * 16 + g + 8 * half;
                const int bb = m >> 11;
                const int s  = m & (SEQLEN - 1);
                const size_t dst = (((size_t)(bb * NHEADS + h) * SEQLEN + s) * DHEAD + col);
                float v0 = acc[am][an][2 * half + 0] + b0;
                float v1 = acc[am][an][2 * half + 1] + b1;
                __nv_bfloat16 h0, l0, h1, l1;
                split1(v0, h0, l0); split1(v1, h1, l1);
                __nv_bfloat162 hp; hp.x = h0; hp.y = h1;
                __nv_bfloat162 lp; lp.x = l0; lp.y = l1;
                *(__nv_bfloat162*)&dhi[dst] = hp;
                *(__nv_bfloat162*)&dlo[dst] = lp;
            }
        }
}

// out proj: grid (M/128, DMODEL/128), block 256
__global__ void __launch_bounds__(256) out_mma_kernel(
    const float* __restrict__ bO, float* __restrict__ out)
{
    extern __shared__ __nv_bfloat16 smem[];
    const int mBase = blockIdx.x * 128;
    const int nBase = blockIdx.y * 128;
    float acc[2][8][4];
    gemm_split_core(gz_hi, gz_lo,
                    gwo_hi + (size_t)nBase * DMODEL, gwo_lo + (size_t)nBase * DMODEL,
                    mBase, acc, smem);

    const int tid = threadIdx.x, wid = tid >> 5, lane = tid & 31;
    const int wm = (wid & 3) * 32, wn = (wid >> 2) * 64;
    const int g = lane >> 2, t = lane & 3;
    float* outBase = out + (size_t)mBase * DMODEL + nBase;
#pragma unroll
    for (int am = 0; am < 2; am++)
#pragma unroll
        for (int an = 0; an < 8; an++) {
            const int col = wn + an * 8 + 2 * t;
            const int r0 = wm + am * 16 + g;
            float b0 = bO[nBase + col], b1 = bO[nBase + col + 1];
            outBase[(size_t)r0 * DMODEL + col]           = acc[am][an][0] + b0;
            outBase[(size_t)r0 * DMODEL + col + 1]       = acc[am][an][1] + b1;
            outBase[(size_t)(r0 + 8) * DMODEL + col]     = acc[am][an][2] + b0;
            outBase[(size_t)(r0 + 8) * DMODEL + col + 1] = acc[am][an][3] + b1;
        }
}

// ---------------------------------------------------------------------------
// Tensor-core flash attention, cp.async 2-stage K/V pipeline, one sync/iter,
// ldmatrix fragment loads (V via ldmatrix.trans).
// grid = (SEQLEN/128, NHEADS, BATCH), block = 256 (8 warps).
// ---------------------------------------------------------------------------
#define ASTR 136
#define AARR (64 * ASTR)
#define ASTAGE (4 * AARR)
#define AQ (128 * ASTR)
#define ATTN_SMEM ((2 * AQ + 2 * ASTAGE) * 2)

__global__ void __launch_bounds__(256, 1) attn_mma_kernel()
{
    const int qt = gridDim.x - 1 - blockIdx.x;
    const int h  = blockIdx.y;
    const int b  = blockIdx.z;
    const int qBase = qt * 128;

    extern __shared__ __nv_bfloat16 smem_a[];
    __nv_bfloat16* sQh = smem_a;
    __nv_bfloat16* sQl = sQh + AQ;
    __nv_bfloat16* kvs = sQl + AQ;

    const int tid = threadIdx.x;
    const int wid = tid >> 5;
    const int lane = tid & 31;
    const int g = lane >> 2;
    const int t = lane & 3;
    const int wrow = wid * 16;

    // ldmatrix lane geometry
    const int lr  = lane & 15;
    const int kof = 8 * (lane >> 4);
    const int vkr = (lane & 7) + 8 * ((lane >> 3) & 1);   // V trans row
    const int vco = 8 * (lane >> 4);                       // V trans col

    const size_t bh = (size_t)(b * NHEADS + h) * SEQLEN * DHEAD;
    const __nv_bfloat16* qh = gq_hi + bh;
    const __nv_bfloat16* ql = gq_lo + bh;
    const __nv_bfloat16* kh = gk_hi + bh;
    const __nv_bfloat16* kl = gk_lo + bh;
    const __nv_bfloat16* vh = gv_hi + bh;
    const __nv_bfloat16* vl = gv_lo + bh;

    const u32 kvbase = (u32)__cvta_generic_to_shared(kvs);
    const u32 qhU = (u32)__cvta_generic_to_shared(sQh) + (u32)(((wrow + lr) * ASTR + kof) * 2);
    const u32 qlU = (u32)__cvta_generic_to_shared(sQl) + (u32)(((wrow + lr) * ASTR + kof) * 2);

    auto issue_kv = [&](int kBase, int st) {
        const u32 b0 = kvbase + (u32)st * (ASTAGE * 2);
#pragma unroll
        for (int it = 0; it < 4; it++) {
            const int idx = tid + it * 256;
            const int r = idx >> 4;
            const int c = idx & 15;
            const u32 doff = (u32)(r * ASTR + c * 8) * 2;
            const size_t goff = (size_t)(kBase + r) * DHEAD + c * 8;
            cpa16(b0 + doff,                kh + goff);
            cpa16(b0 + AARR * 2 + doff,     kl + goff);
            cpa16(b0 + 2 * AARR * 2 + doff, vh + goff);
            cpa16(b0 + 3 * AARR * 2 + doff, vl + goff);
        }
        CP_COMMIT();
    };

    const int nkt = 2 * qt + 2;
    issue_kv(0, 0);

    // Q tile (plain loads; overlaps with in-flight cp.async)
    for (int idx = tid; idx < 128 * 16; idx += 256) {
        const int r = idx >> 4, c8 = (idx & 15) * 8;
        *(uint4*)&sQh[r * ASTR + c8] = *(const uint4*)&qh[(size_t)(qBase + r) * DHEAD + c8];
        *(uint4*)&sQl[r * ASTR + c8] = *(const uint4*)&ql[(size_t)(qBase + r) * DHEAD + c8];
    }

    float o[16][4];
#pragma unroll
    for (int j = 0; j < 16; j++)
#pragma unroll
        for (int c = 0; c < 4; c++) o[j][c] = 0.f;
    float m0 = -1e30f, m1 = -1e30f, l0 = 0.f, l1 = 0.f;

    const float sl2e = 0.08838834764831845f * 1.4426950408889634f;

    for (int kt = 0; kt < nkt; kt++) {
        const int kBase = kt * 64;
        const int cur = kt & 1;
        CP_WAIT0();        // tile kt landed
        __syncthreads();   // visible to all; compute(kt-1) done
        if (kt + 1 < nkt) issue_kv((kt + 1) * 64, 1 - cur);

        if (kBase > qBase + wrow + 15) continue;

        const u32 kvU = kvbase + (u32)cur * (ASTAGE * 2);
        const u32 kH = kvU;
        const u32 kL = kvU + AARR * 2;
        const u32 vH = kvU + 2 * AARR * 2;
        const u32 vL = kvU + 3 * AARR * 2;

        // ---- S = Q K^T
        float sacc[8][4];
#pragma unroll
        for (int an = 0; an < 8; an++)
#pragma unroll
            for (int c = 0; c < 4; c++) sacc[an][c] = 0.f;

#pragma unroll
        for (int ks = 0; ks < DHEAD; ks += 16) {
            u32 ah[4], al[4];
            ldsm_x4(ah, qhU + (u32)(ks * 2));
            ldsm_x4(al, qlU + (u32)(ks * 2));
#pragma unroll
            for (int p = 0; p < 4; p++) {
                const u32 off = (u32)(((p * 16 + lr) * ASTR + ks + kof) * 2);
                u32 rh[4], rl[4];
                ldsm_x4(rh, kH + off);
                ldsm_x4(rl, kL + off);
                u32 b0h[2] = { rh[0], rh[2] };
                u32 b1h[2] = { rh[1], rh[3] };
                u32 b0l[2] = { rl[0], rl[2] };
                u32 b1l[2] = { rl[1], rl[3] };
                MMA_BF16(sacc[2 * p],     ah, b0h);
                MMA_BF16(sacc[2 * p],     ah, b0l);
                MMA_BF16(sacc[2 * p],     al, b0h);
                MMA_BF16(sacc[2 * p + 1], ah, b1h);
                MMA_BF16(sacc[2 * p + 1], ah, b1l);
                MMA_BF16(sacc[2 * p + 1], al, b1h);
            }
        }

        // ---- scale + causal mask (log2 domain)
        const int qr0 = qBase + wrow + g;
        const int qr1 = qr0 + 8;
#pragma unroll
        for (int an = 0; an < 8; an++) {
            const int c0 = kBase + an * 8 + 2 * t;
            sacc[an][0] = (c0     <= qr0) ? sacc[an][0] * sl2e : -1e30f;
            sacc[an][1] = (c0 + 1 <= qr0) ? sacc[an][1] * sl2e : -1e30f;
            sacc[an][2] = (c0     <= qr1) ? sacc[an][2] * sl2e : -1e30f;
            sacc[an][3] = (c0 + 1 <= qr1) ? sacc[an][3] * sl2e : -1e30f;
        }

        // ---- row max
        float mx0 = -1e30f, mx1 = -1e30f;
#pragma unroll
        for (int an = 0; an < 8; an++) {
            mx0 = fmaxf(mx0, fmaxf(sacc[an][0], sacc[an][1]));
            mx1 = fmaxf(mx1, fmaxf(sacc[an][2], sacc[an][3]));
        }
        mx0 = fmaxf(mx0, __shfl_xor_sync(0xffffffffu, mx0, 1));
        mx0 = fmaxf(mx0, __shfl_xor_sync(0xffffffffu, mx0, 2));
        mx1 = fmaxf(mx1, __shfl_xor_sync(0xffffffffu, mx1, 1));
        mx1 = fmaxf(mx1, __shfl_xor_sync(0xffffffffu, mx1, 2));

        const float mn0 = fmaxf(m0, mx0), mn1 = fmaxf(m1, mx1);
        const float al0 = ex2f(m0 - mn0), al1 = ex2f(m1 - mn1);
        m0 = mn0; m1 = mn1;

        // ---- p = 2^(s - m), row sums
        float s0 = 0.f, s1 = 0.f;
#pragma unroll
        for (int an = 0; an < 8; an++) {
            sacc[an][0] = ex2f(sacc[an][0] - mn0);
            sacc[an][1] = ex2f(sacc[an][1] - mn0);
            sacc[an][2] = ex2f(sacc[an][2] - mn1);
            sacc[an][3] = ex2f(sacc[an][3] - mn1);
            s0 += sacc[an][0] + sacc[an][1];
            s1 += sacc[an][2] + sacc[an][3];
        }
        s0 += __shfl_xor_sync(0xffffffffu, s0, 1);
        s0 += __shfl_xor_sync(0xffffffffu, s0, 2);
        s1 += __shfl_xor_sync(0xffffffffu, s1, 1);
        s1 += __shfl_xor_sync(0xffffffffu, s1, 2);
        l0 = l0 * al0 + s0;
        l1 = l1 * al1 + s1;

#pragma unroll
        for (int j = 0; j < 16; j++) {
            o[j][0] *= al0; o[j][1] *= al0;
            o[j][2] *= al1; o[j][3] *= al1;
        }

        // ---- O += P V (V fragments via ldmatrix.trans)
#pragma unroll
        for (int jp = 0; jp < 4; jp++) {
            u32 aph[4], apl[4];
            {
                float p00 = sacc[2 * jp][0],     p01 = sacc[2 * jp][1];
                float p02 = sacc[2 * jp][2],     p03 = sacc[2 * jp][3];
                float p10 = sacc[2 * jp + 1][0], p11 = sacc[2 * jp + 1][1];
                float p12 = sacc[2 * jp + 1][2], p13 = sacc[2 * jp + 1][3];
                __nv_bfloat16 hh, ll;
                float h00, h01, h02, h03, h10, h11, h12, h13;
                split1(p00, hh, ll); h00 = __bfloat162float(hh);
                split1(p01, hh, ll); h01 = __bfloat162float(hh);
                split1(p02, hh, ll); h02 = __bfloat162float(hh);
                split1(p03, hh, ll); h03 = __bfloat162float(hh);
                split1(p10, hh, ll); h10 = __bfloat162float(hh);
                split1(p11, hh, ll); h11 = __bfloat162float(hh);
                split1(p12, hh, ll); h12 = __bfloat162float(hh);
                split1(p13, hh, ll); h13 = __bfloat162float(hh);
                aph[0] = pack2bf(h00, h01);
                aph[1] = pack2bf(h02, h03);
                aph[2] = pack2bf(h10, h11);
                aph[3] = pack2bf(h12, h13);
                apl[0] = pack2bf(p00 - h00, p01 - h01);
                apl[1] = pack2bf(p02 - h02, p03 - h03);
                apl[2] = pack2bf(p10 - h10, p11 - h11);
                apl[3] = pack2bf(p12 - h12, p13 - h13);
            }
            const int ks = 16 * jp;
#pragma unroll
            for (int p = 0; p < 8; p++) {
                const u32 off = (u32)(((ks + vkr) * ASTR + p * 16 + vco) * 2);
                u32 rh[4], rl[4];
                ldsm_x4_t(rh, vH + off);
                ldsm_x4_t(rl, vL + off);
                u32 bh2a[2] = { rh[0], rh[1] };
                u32 bh2b[2] = { rh[2], rh[3] };
                u32 bl2a[2] = { rl[0], rl[1] };
                u32 bl2b[2] = { rl[2], rl[3] };
                MMA_BF16(o[2 * p],     aph, bh2a);
                MMA_BF16(o[2 * p],     aph, bl2a);
                MMA_BF16(o[2 * p],     apl, bh2a);
                MMA_BF16(o[2 * p + 1], aph, bh2b);
                MMA_BF16(o[2 * p + 1], aph, bl2b);
                MMA_BF16(o[2 * p + 1], apl, bh2b);
            }
        }
    }

    const float inv0 = 1.f / l0;
    const float inv1 = 1.f / l1;
    const int r0 = qBase + wrow + g;
#pragma unroll
    for (int an = 0; an < 16; an++) {
        const int col = an * 8 + 2 * t;
#pragma unroll
        for (int half = 0; half < 2; half++) {
            const int row = r0 + 8 * half;
            const float inv = half ? inv1 : inv0;
            float z0 = o[an][2 * half + 0] * inv;
            float z1 = o[an][2 * half + 1] * inv;
            __nv_bfloat16 h0, lo0, h1, lo1;
            split1(z0, h0, lo0); split1(z1, h1, lo1);
            __nv_bfloat162 hp; hp.x = h0; hp.y = h1;
            __nv_bfloat162 lp; lp.x = lo0; lp.y = lo1;
            const size_t dst = ((size_t)(b * SEQLEN + row) * DMODEL + h * DHEAD + col);
            *(__nv_bfloat162*)&gz_hi[dst] = hp;
            *(__nv_bfloat162*)&gz_lo[dst] = lp;
        }
    }
}

// ---------------------------------------------------------------------------
// Launch
// ---------------------------------------------------------------------------
extern "C" void kernel_launch(void* const* d_in, const int* in_sizes, int n_in,
                              void* d_out, int out_size)
{
    const float* x  = (const float*)d_in[0];
    const float* Wq = (const float*)d_in[1];
    const float* Wk = (const float*)d_in[2];
    const float* Wv = (const float*)d_in[3];
    const float* Wo = (const float*)d_in[4];
    const float* bQ = (const float*)d_in[5];
    const float* bK = (const float*)d_in[6];
    const float* bV = (const float*)d_in[7];
    const float* bO = (const float*)d_in[8];
    float* out = (float*)d_out;

    static bool attr_set = false;
    if (!attr_set) {
        cudaFuncSetAttribute(qkv_mma_kernel, cudaFuncAttributeMaxDynamicSharedMemorySize, GEMM_SMEM);
        cudaFuncSetAttribute(out_mma_kernel, cudaFuncAttributeMaxDynamicSharedMemorySize, GEMM_SMEM);
        cudaFuncSetAttribute(attn_mma_kernel, cudaFuncAttributeMaxDynamicSharedMemorySize, ATTN_SMEM);
        attr_set = true;
    }

    // 0) split/transposes
    split_x_kernel<<<(MTOT * DMODEL / 2) / 256, 256>>>(x);
    split_w_kernel<<<dim3(DMODEL / 32, DHEAD / 32, 3 * NHEADS), dim3(32, 8)>>>(Wq, Wk, Wv);
    split_wo_kernel<<<dim3(DMODEL / 32, DMODEL / 32), dim3(32, 8)>>>(Wo);

    // 1) QKV projections (2-stage single-sync pipeline, 2 CTAs/SM, ldmatrix)
    qkv_mma_kernel<<<dim3(MTOT / 128, NHEADS, 3), 256, GEMM_SMEM>>>(bQ, bK, bV);

    // 2) tensor-core flash attention (ldmatrix + ldmatrix.trans)
    attn_mma_kernel<<<dim3(SEQLEN / 128, NHEADS, BATCH), 256, ATTN_SMEM>>>();

    // 3) output projection
    out_mma_kernel<<<dim3(MTOT / 128, DMODEL / 128), 256, GEMM_SMEM>>>(bO, out);

    (void)in_sizes; (void)n_in; (void)out_size;
}

// round 13
// speedup vs baseline: 1.0079x; 1.0079x over previous
#include <cuda_runtime.h>
#include <cuda_bf16.h>
#include <math.h>

// Problem constants
#define BATCH   2
#define SEQLEN  2048
#define DMODEL  2048
#define NHEADS  16
#define DHEAD   128
#define MTOT    (BATCH * SEQLEN)      // 4096

typedef unsigned int u32;
typedef unsigned short u16;

// ---- bf16 split helper: v = hi + lo with ~2^-16 combined relative residual
__device__ __forceinline__ void split1(float v, __nv_bfloat16& h, __nv_bfloat16& l) {
    h = __float2bfloat16(v);
    l = __float2bfloat16(v - __bfloat162float(h));
}
__device__ __forceinline__ u32 pack2bf(float lo, float hi) {
    u32 r; asm("cvt.rn.bf16x2.f32 %0, %1, %2;" : "=r"(r) : "f"(hi), "f"(lo)); return r;
}
__device__ __forceinline__ float ex2f(float x) {
    float y; asm("ex2.approx.f32 %0, %1;" : "=f"(y) : "f"(x)); return y;
}
// ---- cp.async helpers (16B; smem dst MUST be 16B-aligned: row pitch % 16B == 0)
__device__ __forceinline__ void cpa16(u32 dst_smem, const void* src) {
    asm volatile("cp.async.cg.shared.global [%0], [%1], 16;" :: "r"(dst_smem), "l"(src));
}
#define CP_COMMIT() asm volatile("cp.async.commit_group;")
#define CP_WAIT0()  asm volatile("cp.async.wait_group 0;")

// ---- scratch (device globals; device-side refs only)
__device__ __nv_bfloat16 gx_hi[(size_t)MTOT * DMODEL];
__device__ __nv_bfloat16 gx_lo[(size_t)MTOT * DMODEL];
__device__ __nv_bfloat16 gq_hi[(size_t)MTOT * DMODEL];
__device__ __nv_bfloat16 gq_lo[(size_t)MTOT * DMODEL];
__device__ __nv_bfloat16 gk_hi[(size_t)MTOT * DMODEL];
__device__ __nv_bfloat16 gk_lo[(size_t)MTOT * DMODEL];
__device__ __nv_bfloat16 gv_hi[(size_t)MTOT * DMODEL];
__device__ __nv_bfloat16 gv_lo[(size_t)MTOT * DMODEL];
__device__ __nv_bfloat16 gz_hi[(size_t)MTOT * DMODEL];
__device__ __nv_bfloat16 gz_lo[(size_t)MTOT * DMODEL];
// QKV weights transposed per head: [which][h][n(128)][k(2048)]
__device__ __nv_bfloat16 gw_hi[(size_t)3 * NHEADS * DHEAD * DMODEL];
__device__ __nv_bfloat16 gw_lo[(size_t)3 * NHEADS * DHEAD * DMODEL];
// W_O transposed: [n(2048)][k(2048)]
__device__ __nv_bfloat16 gwo_hi[(size_t)DMODEL * DMODEL];
__device__ __nv_bfloat16 gwo_lo[(size_t)DMODEL * DMODEL];

// ---------------------------------------------------------------------------
// Prep kernels
// ---------------------------------------------------------------------------
__global__ void __launch_bounds__(256) split_x_kernel(const float* __restrict__ x)
{
    size_t i = (size_t)blockIdx.x * blockDim.x + threadIdx.x;
    float2 v = ((const float2*)x)[i];
    __nv_bfloat16 h0, l0, h1, l1;
    split1(v.x, h0, l0); split1(v.y, h1, l1);
    __nv_bfloat162 hp; hp.x = h0; hp.y = h1;
    __nv_bfloat162 lp; lp.x = l0; lp.y = l1;
    ((__nv_bfloat162*)gx_hi)[i] = hp;
    ((__nv_bfloat162*)gx_lo)[i] = lp;
}

__global__ void split_w_kernel(const float* __restrict__ Wq,
                               const float* __restrict__ Wk,
                               const float* __restrict__ Wv)
{
    const int which = blockIdx.z / NHEADS;
    const int h     = blockIdx.z % NHEADS;
    const float* W = ((which == 0) ? Wq : (which == 1) ? Wk : Wv)
                     + (size_t)h * DMODEL * DHEAD;
    const int k0 = blockIdx.x * 32;
    const int n0 = blockIdx.y * 32;

    __shared__ float tile[32][33];
    const int tx = threadIdx.x, ty = threadIdx.y;
#pragma unroll
    for (int r = 0; r < 4; r++)
        tile[ty + 8 * r][tx] = W[(size_t)(k0 + ty + 8 * r) * DHEAD + n0 + tx];
    __syncthreads();
    const size_t base = ((size_t)(which * NHEADS + h) * DHEAD);
#pragma unroll
    for (int r = 0; r < 4; r++) {
        float v = tile[tx][ty + 8 * r];
        __nv_bfloat16 hh, ll; split1(v, hh, ll);
        size_t idx = (base + n0 + ty + 8 * r) * DMODEL + k0 + tx;
        gw_hi[idx] = hh; gw_lo[idx] = ll;
    }
}

__global__ void split_wo_kernel(const float* __restrict__ Wo)
{
    const int k0 = blockIdx.x * 32;
    const int n0 = blockIdx.y * 32;
    __shared__ float tile[32][33];
    const int tx = threadIdx.x, ty = threadIdx.y;
#pragma unroll
    for (int r = 0; r < 4; r++)
        tile[ty + 8 * r][tx] = Wo[(size_t)(k0 + ty + 8 * r) * DMODEL + n0 + tx];
    __syncthreads();
#pragma unroll
    for (int r = 0; r < 4; r++) {
        float v = tile[tx][ty + 8 * r];
        __nv_bfloat16 hh, ll; split1(v, hh, ll);
        size_t idx = (size_t)(n0 + ty + 8 * r) * DMODEL + k0 + tx;
        gwo_hi[idx] = hh; gwo_lo[idx] = ll;
    }
}

// ---------------------------------------------------------------------------
// bf16 split-GEMM core (mma m16n8k16, 3-term), cp.async 2-stage pipeline,
// ONE __syncthreads per K-iteration, 80 KB smem -> 2 CTAs/SM.
// Split-term loop hoisted OUTERMOST: 16 independent MMAs between acc reuses.
// Block 256 thr (8 warps, 4x2), tile 128x128, K step 32.
// ---------------------------------------------------------------------------
#define KC   32
#define SSTR 40
#define GARR  (128 * SSTR)          // elems per array per stage
#define GSTAGE (4 * GARR)           // elems per stage
#define GEMM_SMEM (2 * GSTAGE * 2)  // 81920 bytes

#define MMA_BF16(c, a, b) \
    asm volatile("mma.sync.aligned.m16n8k16.row.col.f32.bf16.bf16.f32 " \
        "{%0,%1,%2,%3}, {%4,%5,%6,%7}, {%8,%9}, {%0,%1,%2,%3};" \
        : "+f"((c)[0]), "+f"((c)[1]), "+f"((c)[2]), "+f"((c)[3]) \
        : "r"((a)[0]), "r"((a)[1]), "r"((a)[2]), "r"((a)[3]), \
          "r"((b)[0]), "r"((b)[1]))

__device__ __forceinline__ void gemm_split_core(
    const __nv_bfloat16* __restrict__ Ah, const __nv_bfloat16* __restrict__ Al,
    const __nv_bfloat16* __restrict__ Bh, const __nv_bfloat16* __restrict__ Bl,
    int mBase, float acc[2][8][4], __nv_bfloat16* smem)
{
    const int tid  = threadIdx.x;
    const int wid  = tid >> 5;
    const int lane = tid & 31;
    const int wm = (wid & 3) * 32;
    const int wn = (wid >> 2) * 64;
    const int g = lane >> 2;
    const int t = lane & 3;

    const u32 sbase = (u32)__cvta_generic_to_shared(smem);

#pragma unroll
    for (int am = 0; am < 2; am++)
#pragma unroll
        for (int an = 0; an < 8; an++)
#pragma unroll
            for (int c = 0; c < 4; c++) acc[am][an][c] = 0.f;

    // issue one K-tile (4 arrays x 128 rows x 32 bf16 = 512 x 16B chunks each)
    auto issue_tile = [&](int k0, int st) {
        const u32 b0 = sbase + (u32)st * (GSTAGE * 2);
#pragma unroll
        for (int it = 0; it < 2; it++) {
            const int idx = tid + it * 256;      // 0..511
            const int r = idx >> 2;
            const int c = idx & 3;
            const u32 doff = (u32)(r * SSTR + c * 8) * 2;
            const size_t aoff = (size_t)(mBase + r) * DMODEL + k0 + c * 8;
            const size_t boff = (size_t)r * DMODEL + k0 + c * 8;
            cpa16(b0 + doff,                 Ah + aoff);
            cpa16(b0 + GARR * 2 + doff,      Al + aoff);
            cpa16(b0 + 2 * GARR * 2 + doff,  Bh + boff);
            cpa16(b0 + 3 * GARR * 2 + doff,  Bl + boff);
        }
        CP_COMMIT();
    };

    const int NKT = DMODEL / KC;   // 64
    issue_tile(0, 0);

    for (int kt = 0; kt < NKT; kt++) {
        const int cur = kt & 1;
        CP_WAIT0();        // tile kt landed (only group outstanding)
        __syncthreads();   // tile kt visible to all; compute(kt-1) on 1-cur done
        if (kt + 1 < NKT) issue_tile((kt + 1) * KC, 1 - cur);

        const __nv_bfloat16* sAh = smem + cur * GSTAGE;
        const __nv_bfloat16* sAl = sAh + GARR;
        const __nv_bfloat16* sBh = sAl + GARR;
        const __nv_bfloat16* sBl = sBh + GARR;

#pragma unroll
        for (int ks = 0; ks < KC; ks += 16) {
            u32 afh[2][4], afl[2][4];
#pragma unroll
            for (int am = 0; am < 2; am++) {
                const int r0 = wm + am * 16 + g;
                afh[am][0] = *(const u32*)&sAh[(r0    ) * SSTR + ks + 2 * t];
                afh[am][1] = *(const u32*)&sAh[(r0 + 8) * SSTR + ks + 2 * t];
                afh[am][2] = *(const u32*)&sAh[(r0    ) * SSTR + ks + 2 * t + 8];
                afh[am][3] = *(const u32*)&sAh[(r0 + 8) * SSTR + ks + 2 * t + 8];
                afl[am][0] = *(const u32*)&sAl[(r0    ) * SSTR + ks + 2 * t];
                afl[am][1] = *(const u32*)&sAl[(r0 + 8) * SSTR + ks + 2 * t];
                afl[am][2] = *(const u32*)&sAl[(r0    ) * SSTR + ks + 2 * t + 8];
                afl[am][3] = *(const u32*)&sAl[(r0 + 8) * SSTR + ks + 2 * t + 8];
            }
            u32 bfh[8][2], bfl[8][2];
#pragma unroll
            for (int an = 0; an < 8; an++) {
                const int n = wn + an * 8 + g;
                bfh[an][0] = *(const u32*)&sBh[n * SSTR + ks + 2 * t];
                bfh[an][1] = *(const u32*)&sBh[n * SSTR + ks + 2 * t + 8];
                bfl[an][0] = *(const u32*)&sBl[n * SSTR + ks + 2 * t];
                bfl[an][1] = *(const u32*)&sBl[n * SSTR + ks + 2 * t + 8];
            }
            // term-major order: 16 independent MMAs between reuses of each acc
#pragma unroll
            for (int am = 0; am < 2; am++)
#pragma unroll
                for (int an = 0; an < 8; an++)
                    MMA_BF16(acc[am][an], afh[am], bfh[an]);
#pragma unroll
            for (int am = 0; am < 2; am++)
#pragma unroll
                for (int an = 0; an < 8; an++)
                    MMA_BF16(acc[am][an], afh[am], bfl[an]);
#pragma unroll
            for (int am = 0; am < 2; am++)
#pragma unroll
                for (int an = 0; an < 8; an++)
                    MMA_BF16(acc[am][an], afl[am], bfh[an]);
        }
    }
}

// QKV: grid (M/128, NHEADS, 3), block 256. Writes split q/k/v in [b,h,s,d].
__global__ void __launch_bounds__(256) qkv_mma_kernel(
    const float* __restrict__ bQ, const float* __restrict__ bK, const float* __restrict__ bV)
{
    extern __shared__ __nv_bfloat16 smem[];
    const int mBase = blockIdx.x * 128;
    const int h     = blockIdx.y;
    const int which = blockIdx.z;
    const float* bias = ((which == 0) ? bQ : (which == 1) ? bK : bV) + h * DHEAD;
    __nv_bfloat16* dhi = (which == 0) ? gq_hi : (which == 1) ? gk_hi : gv_hi;
    __nv_bfloat16* dlo = (which == 0) ? gq_lo : (which == 1) ? gk_lo : gv_lo;
    const __nv_bfloat16* Bh = gw_hi + (size_t)(which * NHEADS + h) * DHEAD * DMODEL;
    const __nv_bfloat16* Bl = gw_lo + (size_t)(which * NHEADS + h) * DHEAD * DMODEL;

    float acc[2][8][4];
    gemm_split_core(gx_hi, gx_lo, Bh, Bl, mBase, acc, smem);

    const int tid = threadIdx.x, wid = tid >> 5, lane = tid & 31;
    const int wm = (wid & 3) * 32, wn = (wid >> 2) * 64;
    const int g = lane >> 2, t = lane & 3;

#pragma unroll
    for (int am = 0; am < 2; am++)
#pragma unroll
        for (int an = 0; an < 8; an++) {
            const int col = wn + an * 8 + 2 * t;
            const float b0 = bias[col], b1 = bias[col + 1];
#pragma unroll
            for (int half = 0; half < 2; half++) {
                const int m = mBase + wm + am * 16 + g + 8 * half;
                const int bb = m >> 11;
                const int s  = m & (SEQLEN - 1);
                const size_t dst = (((size_t)(bb * NHEADS + h) * SEQLEN + s) * DHEAD + col);
                float v0 = acc[am][an][2 * half + 0] + b0;
                float v1 = acc[am][an][2 * half + 1] + b1;
                __nv_bfloat16 h0, l0, h1, l1;
                split1(v0, h0, l0); split1(v1, h1, l1);
                __nv_bfloat162 hp; hp.x = h0; hp.y = h1;
                __nv_bfloat162 lp; lp.x = l0; lp.y = l1;
                *(__nv_bfloat162*)&dhi[dst] = hp;
                *(__nv_bfloat162*)&dlo[dst] = lp;
            }
        }
}

// out proj: grid (M/128, DMODEL/128), block 256
__global__ void __launch_bounds__(256) out_mma_kernel(
    const float* __restrict__ bO, float* __restrict__ out)
{
    extern __shared__ __nv_bfloat16 smem[];
    const int mBase = blockIdx.x * 128;
    const int nBase = blockIdx.y * 128;
    float acc[2][8][4];
    gemm_split_core(gz_hi, gz_lo,
                    gwo_hi + (size_t)nBase * DMODEL, gwo_lo + (size_t)nBase * DMODEL,
                    mBase, acc, smem);

    const int tid = threadIdx.x, wid = tid >> 5, lane = tid & 31;
    const int wm = (wid & 3) * 32, wn = (wid >> 2) * 64;
    const int g = lane >> 2, t = lane & 3;
    float* outBase = out + (size_t)mBase * DMODEL + nBase;
#pragma unroll
    for (int am = 0; am < 2; am++)
#pragma unroll
        for (int an = 0; an < 8; an++) {
            const int col = wn + an * 8 + 2 * t;
            const int r0 = wm + am * 16 + g;
            float b0 = bO[nBase + col], b1 = bO[nBase + col + 1];
            outBase[(size_t)r0 * DMODEL + col]           = acc[am][an][0] + b0;
            outBase[(size_t)r0 * DMODEL + col + 1]       = acc[am][an][1] + b1;
            outBase[(size_t)(r0 + 8) * DMODEL + col]     = acc[am][an][2] + b0;
            outBase[(size_t)(r0 + 8) * DMODEL + col + 1] = acc[am][an][3] + b1;
        }
}

// ---------------------------------------------------------------------------
// Tensor-core flash attention, cp.async 2-stage K/V pipeline, one sync/iter,
// split-term loops hoisted for dependency relief.
// grid = (SEQLEN/128, NHEADS, BATCH), block = 256 (8 warps).
// ---------------------------------------------------------------------------
#define ASTR 136
#define AARR (64 * ASTR)
#define ASTAGE (4 * AARR)
#define AQ (128 * ASTR)
#define ATTN_SMEM ((2 * AQ + 2 * ASTAGE) * 2)

__global__ void __launch_bounds__(256, 1) attn_mma_kernel()
{
    const int qt = gridDim.x - 1 - blockIdx.x;
    const int h  = blockIdx.y;
    const int b  = blockIdx.z;
    const int qBase = qt * 128;

    extern __shared__ __nv_bfloat16 smem_a[];
    __nv_bfloat16* sQh = smem_a;
    __nv_bfloat16* sQl = sQh + AQ;
    __nv_bfloat16* kvs = sQl + AQ;

    const int tid = threadIdx.x;
    const int wid = tid >> 5;
    const int lane = tid & 31;
    const int g = lane >> 2;
    const int t = lane & 3;
    const int wrow = wid * 16;

    const size_t bh = (size_t)(b * NHEADS + h) * SEQLEN * DHEAD;
    const __nv_bfloat16* qh = gq_hi + bh;
    const __nv_bfloat16* ql = gq_lo + bh;
    const __nv_bfloat16* kh = gk_hi + bh;
    const __nv_bfloat16* kl = gk_lo + bh;
    const __nv_bfloat16* vh = gv_hi + bh;
    const __nv_bfloat16* vl = gv_lo + bh;

    const u32 kvbase = (u32)__cvta_generic_to_shared(kvs);

    auto issue_kv = [&](int kBase, int st) {
        const u32 b0 = kvbase + (u32)st * (ASTAGE * 2);
#pragma unroll
        for (int it = 0; it < 4; it++) {
            const int idx = tid + it * 256;
            const int r = idx >> 4;
            const int c = idx & 15;
            const u32 doff = (u32)(r * ASTR + c * 8) * 2;
            const size_t goff = (size_t)(kBase + r) * DHEAD + c * 8;
            cpa16(b0 + doff,                kh + goff);
            cpa16(b0 + AARR * 2 + doff,     kl + goff);
            cpa16(b0 + 2 * AARR * 2 + doff, vh + goff);
            cpa16(b0 + 3 * AARR * 2 + doff, vl + goff);
        }
        CP_COMMIT();
    };

    const int nkt = 2 * qt + 2;
    issue_kv(0, 0);

    for (int idx = tid; idx < 128 * 16; idx += 256) {
        const int r = idx >> 4, c8 = (idx & 15) * 8;
        *(uint4*)&sQh[r * ASTR + c8] = *(const uint4*)&qh[(size_t)(qBase + r) * DHEAD + c8];
        *(uint4*)&sQl[r * ASTR + c8] = *(const uint4*)&ql[(size_t)(qBase + r) * DHEAD + c8];
    }

    float o[16][4];
#pragma unroll
    for (int j = 0; j < 16; j++)
#pragma unroll
        for (int c = 0; c < 4; c++) o[j][c] = 0.f;
    float m0 = -1e30f, m1 = -1e30f, l0 = 0.f, l1 = 0.f;

    const float sl2e = 0.08838834764831845f * 1.4426950408889634f;

    for (int kt = 0; kt < nkt; kt++) {
        const int kBase = kt * 64;
        const int cur = kt & 1;
        CP_WAIT0();
        __syncthreads();
        if (kt + 1 < nkt) issue_kv((kt + 1) * 64, 1 - cur);

        if (kBase > qBase + wrow + 15) continue;

        const __nv_bfloat16* sKh = kvs + cur * ASTAGE;
        const __nv_bfloat16* sKl = sKh + AARR;
        const __nv_bfloat16* sVh = sKl + AARR;
        const __nv_bfloat16* sVl = sVh + AARR;

        float sacc[8][4];
#pragma unroll
        for (int an = 0; an < 8; an++)
#pragma unroll
            for (int c = 0; c < 4; c++) sacc[an][c] = 0.f;

#pragma unroll
        for (int ks = 0; ks < DHEAD; ks += 16) {
            u32 ah[4], al[4];
            const int r0 = wrow + g;
            ah[0] = *(const u32*)&sQh[(r0    ) * ASTR + ks + 2 * t];
            ah[1] = *(const u32*)&sQh[(r0 + 8) * ASTR + ks + 2 * t];
            ah[2] = *(const u32*)&sQh[(r0    ) * ASTR + ks + 2 * t + 8];
            ah[3] = *(const u32*)&sQh[(r0 + 8) * ASTR + ks + 2 * t + 8];
            al[0] = *(const u32*)&sQl[(r0    ) * ASTR + ks + 2 * t];
            al[1] = *(const u32*)&sQl[(r0 + 8) * ASTR + ks + 2 * t];
            al[2] = *(const u32*)&sQl[(r0    ) * ASTR + ks + 2 * t + 8];
            al[3] = *(const u32*)&sQl[(r0 + 8) * ASTR + ks + 2 * t + 8];
            u32 bh2[8][2], bl2[8][2];
#pragma unroll
            for (int an = 0; an < 8; an++) {
                const int n = an * 8 + g;
                bh2[an][0] = *(const u32*)&sKh[n * ASTR + ks + 2 * t];
                bh2[an][1] = *(const u32*)&sKh[n * ASTR + ks + 2 * t + 8];
                bl2[an][0] = *(const u32*)&sKl[n * ASTR + ks + 2 * t];
                bl2[an][1] = *(const u32*)&sKl[n * ASTR + ks + 2 * t + 8];
            }
            // term-major: 8 independent MMAs between acc reuses
#pragma unroll
            for (int an = 0; an < 8; an++) MMA_BF16(sacc[an], ah, bh2[an]);
#pragma unroll
            for (int an = 0; an < 8; an++) MMA_BF16(sacc[an], ah, bl2[an]);
#pragma unroll
            for (int an = 0; an < 8; an++) MMA_BF16(sacc[an], al, bh2[an]);
        }

        const int qr0 = qBase + wrow + g;
        const int qr1 = qr0 + 8;
#pragma unroll
        for (int an = 0; an < 8; an++) {
            const int c0 = kBase + an * 8 + 2 * t;
            sacc[an][0] = (c0     <= qr0) ? sacc[an][0] * sl2e : -1e30f;
            sacc[an][1] = (c0 + 1 <= qr0) ? sacc[an][1] * sl2e : -1e30f;
            sacc[an][2] = (c0     <= qr1) ? sacc[an][2] * sl2e : -1e30f;
            sacc[an][3] = (c0 + 1 <= qr1) ? sacc[an][3] * sl2e : -1e30f;
        }

        float mx0 = -1e30f, mx1 = -1e30f;
#pragma unroll
        for (int an = 0; an < 8; an++) {
            mx0 = fmaxf(mx0, fmaxf(sacc[an][0], sacc[an][1]));
            mx1 = fmaxf(mx1, fmaxf(sacc[an][2], sacc[an][3]));
        }
        mx0 = fmaxf(mx0, __shfl_xor_sync(0xffffffffu, mx0, 1));
        mx0 = fmaxf(mx0, __shfl_xor_sync(0xffffffffu, mx0, 2));
        mx1 = fmaxf(mx1, __shfl_xor_sync(0xffffffffu, mx1, 1));
        mx1 = fmaxf(mx1, __shfl_xor_sync(0xffffffffu, mx1, 2));

        const float mn0 = fmaxf(m0, mx0), mn1 = fmaxf(m1, mx1);
        const float al0 = ex2f(m0 - mn0), al1 = ex2f(m1 - mn1);
        m0 = mn0; m1 = mn1;

        float s0 = 0.f, s1 = 0.f;
#pragma unroll
        for (int an = 0; an < 8; an++) {
            sacc[an][0] = ex2f(sacc[an][0] - mn0);
            sacc[an][1] = ex2f(sacc[an][1] - mn0);
            sacc[an][2] = ex2f(sacc[an][2] - mn1);
            sacc[an][3] = ex2f(sacc[an][3] - mn1);
            s0 += sacc[an][0] + sacc[an][1];
            s1 += sacc[an][2] + sacc[an][3];
        }
        s0 += __shfl_xor_sync(0xffffffffu, s0, 1);
        s0 += __shfl_xor_sync(0xffffffffu, s0, 2);
        s1 += __shfl_xor_sync(0xffffffffu, s1, 1);
        s1 += __shfl_xor_sync(0xffffffffu, s1, 2);
        l0 = l0 * al0 + s0;
        l1 = l1 * al1 + s1;

#pragma unroll
        for (int j = 0; j < 16; j++) {
            o[j][0] *= al0; o[j][1] *= al0;
            o[j][2] *= al1; o[j][3] *= al1;
        }

        const u16* sVh16 = (const u16*)sVh;
        const u16* sVl16 = (const u16*)sVl;
#pragma unroll
        for (int jp = 0; jp < 4; jp++) {
            u32 aph[4], apl[4];
            {
                float p00 = sacc[2 * jp][0],     p01 = sacc[2 * jp][1];
                float p02 = sacc[2 * jp][2],     p03 = sacc[2 * jp][3];
                float p10 = sacc[2 * jp + 1][0], p11 = sacc[2 * jp + 1][1];
                float p12 = sacc[2 * jp + 1][2], p13 = sacc[2 * jp + 1][3];
                __nv_bfloat16 hh, ll;
                float h00, h01, h02, h03, h10, h11, h12, h13;
                split1(p00, hh, ll); h00 = __bfloat162float(hh);
                split1(p01, hh, ll); h01 = __bfloat162float(hh);
                split1(p02, hh, ll); h02 = __bfloat162float(hh);
                split1(p03, hh, ll); h03 = __bfloat162float(hh);
                split1(p10, hh, ll); h10 = __bfloat162float(hh);
                split1(p11, hh, ll); h11 = __bfloat162float(hh);
                split1(p12, hh, ll); h12 = __bfloat162float(hh);
                split1(p13, hh, ll); h13 = __bfloat162float(hh);
                aph[0] = pack2bf(h00, h01);
                aph[1] = pack2bf(h02, h03);
                aph[2] = pack2bf(h10, h11);
                aph[3] = pack2bf(h12, h13);
                apl[0] = pack2bf(p00 - h00, p01 - h01);
                apl[1] = pack2bf(p02 - h02, p03 - h03);
                apl[2] = pack2bf(p10 - h10, p11 - h11);
                apl[3] = pack2bf(p12 - h12, p13 - h13);
            }
            const int ks = 16 * jp;
            // gather V fragments for all 16 n-tiles, then term-major MMAs
#pragma unroll
            for (int anp = 0; anp < 2; anp++) {
                u32 vbh[8][2], vbl[8][2];
#pragma unroll
                for (int aj = 0; aj < 8; aj++) {
                    const int n = (anp * 8 + aj) * 8 + g;
                    u32 v0 = sVh16[(ks + 2 * t)     * ASTR + n];
                    u32 v1 = sVh16[(ks + 2 * t + 1) * ASTR + n];
                    u32 v8 = sVh16[(ks + 2 * t + 8) * ASTR + n];
                    u32 v9 = sVh16[(ks + 2 * t + 9) * ASTR + n];
                    vbh[aj][0] = v0 | (v1 << 16);
                    vbh[aj][1] = v8 | (v9 << 16);
                    v0 = sVl16[(ks + 2 * t)     * ASTR + n];
                    v1 = sVl16[(ks + 2 * t + 1) * ASTR + n];
                    v8 = sVl16[(ks + 2 * t + 8) * ASTR + n];
                    v9 = sVl16[(ks + 2 * t + 9) * ASTR + n];
                    vbl[aj][0] = v0 | (v1 << 16);
                    vbl[aj][1] = v8 | (v9 << 16);
                }
#pragma unroll
                for (int aj = 0; aj < 8; aj++) MMA_BF16(o[anp * 8 + aj], aph, vbh[aj]);
#pragma unroll
                for (int aj = 0; aj < 8; aj++) MMA_BF16(o[anp * 8 + aj], aph, vbl[aj]);
#pragma unroll
                for (int aj = 0; aj < 8; aj++) MMA_BF16(o[anp * 8 + aj], apl, vbh[aj]);
            }
        }
    }

    const float inv0 = 1.f / l0;
    const float inv1 = 1.f / l1;
    const int r0 = qBase + wrow + g;
#pragma unroll
    for (int an = 0; an < 16; an++) {
        const int col = an * 8 + 2 * t;
#pragma unroll
        for (int half = 0; half < 2; half++) {
            const int row = r0 + 8 * half;
            const float inv = half ? inv1 : inv0;
            float z0 = o[an][2 * half + 0] * inv;
            float z1 = o[an][2 * half + 1] * inv;
            __nv_bfloat16 h0, lo0, h1, lo1;
            split1(z0, h0, lo0); split1(z1, h1, lo1);
            __nv_bfloat162 hp; hp.x = h0; hp.y = h1;
            __nv_bfloat162 lp; lp.x = lo0; lp.y = lo1;
            const size_t dst = ((size_t)(b * SEQLEN + row) * DMODEL + h * DHEAD + col);
            *(__nv_bfloat162*)&gz_hi[dst] = hp;
            *(__nv_bfloat162*)&gz_lo[dst] = lp;
        }
    }
}

// ---------------------------------------------------------------------------
// Launch
// ---------------------------------------------------------------------------
extern "C" void kernel_launch(void* const* d_in, const int* in_sizes, int n_in,
                              void* d_out, int out_size)
{
    const float* x  = (const float*)d_in[0];
    const float* Wq = (const float*)d_in[1];
    const float* Wk = (const float*)d_in[2];
    const float* Wv = (const float*)d_in[3];
    const float* Wo = (const float*)d_in[4];
    const float* bQ = (const float*)d_in[5];
    const float* bK = (const float*)d_in[6];
    const float* bV = (const float*)d_in[7];
    const float* bO = (const float*)d_in[8];
    float* out = (float*)d_out;

    static bool attr_set = false;
    if (!attr_set) {
        cudaFuncSetAttribute(qkv_mma_kernel, cudaFuncAttributeMaxDynamicSharedMemorySize, GEMM_SMEM);
        cudaFuncSetAttribute(out_mma_kernel, cudaFuncAttributeMaxDynamicSharedMemorySize, GEMM_SMEM);
        cudaFuncSetAttribute(attn_mma_kernel, cudaFuncAttributeMaxDynamicSharedMemorySize, ATTN_SMEM);
        attr_set = true;
    }

    // 0) split/transposes
    split_x_kernel<<<(MTOT * DMODEL / 2) / 256, 256>>>(x);
    split_w_kernel<<<dim3(DMODEL / 32, DHEAD / 32, 3 * NHEADS), dim3(32, 8)>>>(Wq, Wk, Wv);
    split_wo_kernel<<<dim3(DMODEL / 32, DMODEL / 32), dim3(32, 8)>>>(Wo);

    // 1) QKV projections (2-stage single-sync, 2 CTAs/SM, term-major MMAs)
    qkv_mma_kernel<<<dim3(MTOT / 128, NHEADS, 3), 256, GEMM_SMEM>>>(bQ, bK, bV);

    // 2) tensor-core flash attention (term-major MMAs)
    attn_mma_kernel<<<dim3(SEQLEN / 128, NHEADS, BATCH), 256, ATTN_SMEM>>>();

    // 3) output projection
    out_mma_kernel<<<dim3(MTOT / 128, DMODEL / 128), 256, GEMM_SMEM>>>(bO, out);

    (void)in_sizes; (void)n_in; (void)out_size;
}

// round 14
// speedup vs baseline: 1.3054x; 1.2951x over previous
#include <cuda_runtime.h>
#include <cuda_bf16.h>
#include <cuda_fp16.h>
#include <math.h>

// Problem constants
#define BATCH   2
#define SEQLEN  2048
#define DMODEL  2048
#define NHEADS  16
#define DHEAD   128
#define MTOT    (BATCH * SEQLEN)      // 4096

typedef unsigned int u32;
typedef unsigned short u16;

// ---- bf16 split helper (attention path): v = hi + lo
__device__ __forceinline__ void split1(float v, __nv_bfloat16& h, __nv_bfloat16& l) {
    h = __float2bfloat16(v);
    l = __float2bfloat16(v - __bfloat162float(h));
}
// ---- fp16 split helper (weights): v = hi + lo, residual ~2^-22
__device__ __forceinline__ void split1h(float v, __half& h, __half& l) {
    h = __float2half(v);
    l = __float2half(v - __half2float(h));
}
__device__ __forceinline__ u32 pack2bf(float lo, float hi) {
    u32 r; asm("cvt.rn.bf16x2.f32 %0, %1, %2;" : "=r"(r) : "f"(hi), "f"(lo)); return r;
}
__device__ __forceinline__ float ex2f(float x) {
    float y; asm("ex2.approx.f32 %0, %1;" : "=f"(y) : "f"(x)); return y;
}
// ---- cp.async helpers (16B; smem dst MUST be 16B-aligned: row pitch % 16B == 0)
__device__ __forceinline__ void cpa16(u32 dst_smem, const void* src) {
    asm volatile("cp.async.cg.shared.global [%0], [%1], 16;" :: "r"(dst_smem), "l"(src));
}
#define CP_COMMIT() asm volatile("cp.async.commit_group;")
#define CP_WAIT0()  asm volatile("cp.async.wait_group 0;")

// ---- scratch (device globals; device-side refs only)
__device__ __half        gx16[(size_t)MTOT * DMODEL];          // x as fp16
__device__ __nv_bfloat16 gq_hi[(size_t)MTOT * DMODEL];
__device__ __nv_bfloat16 gq_lo[(size_t)MTOT * DMODEL];
__device__ __nv_bfloat16 gk_hi[(size_t)MTOT * DMODEL];
__device__ __nv_bfloat16 gk_lo[(size_t)MTOT * DMODEL];
__device__ __nv_bfloat16 gv_hi[(size_t)MTOT * DMODEL];
__device__ __nv_bfloat16 gv_lo[(size_t)MTOT * DMODEL];
__device__ __half        gz16[(size_t)MTOT * DMODEL];          // z as fp16
// QKV weights transposed per head, fp16 split: [which][h][n(128)][k(2048)]
__device__ __half gw16_hi[(size_t)3 * NHEADS * DHEAD * DMODEL];
__device__ __half gw16_lo[(size_t)3 * NHEADS * DHEAD * DMODEL];
// W_O transposed, fp16 split: [n(2048)][k(2048)]
__device__ __half gwo16_hi[(size_t)DMODEL * DMODEL];
__device__ __half gwo16_lo[(size_t)DMODEL * DMODEL];

// ---------------------------------------------------------------------------
// Prep kernels
// ---------------------------------------------------------------------------
__global__ void __launch_bounds__(256) split_x_kernel(const float* __restrict__ x)
{
    size_t i = (size_t)blockIdx.x * blockDim.x + threadIdx.x;   // pair index
    float2 v = ((const float2*)x)[i];
    __half2 hp; hp.x = __float2half(v.x); hp.y = __float2half(v.y);
    ((__half2*)gx16)[i] = hp;
}

__global__ void split_w_kernel(const float* __restrict__ Wq,
                               const float* __restrict__ Wk,
                               const float* __restrict__ Wv)
{
    const int which = blockIdx.z / NHEADS;
    const int h     = blockIdx.z % NHEADS;
    const float* W = ((which == 0) ? Wq : (which == 1) ? Wk : Wv)
                     + (size_t)h * DMODEL * DHEAD;
    const int k0 = blockIdx.x * 32;
    const int n0 = blockIdx.y * 32;

    __shared__ float tile[32][33];
    const int tx = threadIdx.x, ty = threadIdx.y;
#pragma unroll
    for (int r = 0; r < 4; r++)
        tile[ty + 8 * r][tx] = W[(size_t)(k0 + ty + 8 * r) * DHEAD + n0 + tx];
    __syncthreads();
    const size_t base = ((size_t)(which * NHEADS + h) * DHEAD);
#pragma unroll
    for (int r = 0; r < 4; r++) {
        float v = tile[tx][ty + 8 * r];
        __half hh, ll; split1h(v, hh, ll);
        size_t idx = (base + n0 + ty + 8 * r) * DMODEL + k0 + tx;
        gw16_hi[idx] = hh; gw16_lo[idx] = ll;
    }
}

__global__ void split_wo_kernel(const float* __restrict__ Wo)
{
    const int k0 = blockIdx.x * 32;
    const int n0 = blockIdx.y * 32;
    __shared__ float tile[32][33];
    const int tx = threadIdx.x, ty = threadIdx.y;
#pragma unroll
    for (int r = 0; r < 4; r++)
        tile[ty + 8 * r][tx] = Wo[(size_t)(k0 + ty + 8 * r) * DMODEL + n0 + tx];
    __syncthreads();
#pragma unroll
    for (int r = 0; r < 4; r++) {
        float v = tile[tx][ty + 8 * r];
        __half hh, ll; split1h(v, hh, ll);
        size_t idx = (size_t)(n0 + ty + 8 * r) * DMODEL + k0 + tx;
        gwo16_hi[idx] = hh; gwo16_lo[idx] = ll;
    }
}

// ---------------------------------------------------------------------------
// fp16 2-term GEMM core: C = A16·Bh + A16·Bl (error only from A rounding).
// cp.async 2-stage, one sync/iter, 3 arrays x 10 KB/stage -> 60 KB, 2 CTAs/SM.
// Block 256 thr (8 warps, 4x2), tile 128x128, K step 32.
// ---------------------------------------------------------------------------
#define KC   32
#define SSTR 40
#define GARR  (128 * SSTR)          // elems per array per stage
#define GSTAGE (3 * GARR)           // elems per stage (A16, Bh, Bl)
#define GEMM_SMEM (2 * GSTAGE * 2)  // 61440 bytes

#define MMA_F16(c, a, b) \
    asm volatile("mma.sync.aligned.m16n8k16.row.col.f32.f16.f16.f32 " \
        "{%0,%1,%2,%3}, {%4,%5,%6,%7}, {%8,%9}, {%0,%1,%2,%3};" \
        : "+f"((c)[0]), "+f"((c)[1]), "+f"((c)[2]), "+f"((c)[3]) \
        : "r"((a)[0]), "r"((a)[1]), "r"((a)[2]), "r"((a)[3]), \
          "r"((b)[0]), "r"((b)[1]))

#define MMA_BF16(c, a, b) \
    asm volatile("mma.sync.aligned.m16n8k16.row.col.f32.bf16.bf16.f32 " \
        "{%0,%1,%2,%3}, {%4,%5,%6,%7}, {%8,%9}, {%0,%1,%2,%3};" \
        : "+f"((c)[0]), "+f"((c)[1]), "+f"((c)[2]), "+f"((c)[3]) \
        : "r"((a)[0]), "r"((a)[1]), "r"((a)[2]), "r"((a)[3]), \
          "r"((b)[0]), "r"((b)[1]))

__device__ __forceinline__ void gemm16_core(
    const __half* __restrict__ A16,
    const __half* __restrict__ Bh, const __half* __restrict__ Bl,
    int mBase, float acc[2][8][4], __half* smem)
{
    const int tid  = threadIdx.x;
    const int wid  = tid >> 5;
    const int lane = tid & 31;
    const int wm = (wid & 3) * 32;
    const int wn = (wid >> 2) * 64;
    const int g = lane >> 2;
    const int t = lane & 3;

    const u32 sbase = (u32)__cvta_generic_to_shared(smem);

#pragma unroll
    for (int am = 0; am < 2; am++)
#pragma unroll
        for (int an = 0; an < 8; an++)
#pragma unroll
            for (int c = 0; c < 4; c++) acc[am][an][c] = 0.f;

    // issue one K-tile (3 arrays x 128 rows x 32 fp16 = 512 x 16B chunks each)
    auto issue_tile = [&](int k0, int st) {
        const u32 b0 = sbase + (u32)st * (GSTAGE * 2);
#pragma unroll
        for (int it = 0; it < 2; it++) {
            const int idx = tid + it * 256;      // 0..511
            const int r = idx >> 2;
            const int c = idx & 3;
            const u32 doff = (u32)(r * SSTR + c * 8) * 2;
            const size_t aoff = (size_t)(mBase + r) * DMODEL + k0 + c * 8;
            const size_t boff = (size_t)r * DMODEL + k0 + c * 8;
            cpa16(b0 + doff,                 A16 + aoff);
            cpa16(b0 + GARR * 2 + doff,      Bh + boff);
            cpa16(b0 + 2 * GARR * 2 + doff,  Bl + boff);
        }
        CP_COMMIT();
    };

    const int NKT = DMODEL / KC;   // 64
    issue_tile(0, 0);

    for (int kt = 0; kt < NKT; kt++) {
        const int cur = kt & 1;
        CP_WAIT0();        // tile kt landed (only group outstanding)
        __syncthreads();   // tile kt visible to all; compute(kt-1) on 1-cur done
        if (kt + 1 < NKT) issue_tile((kt + 1) * KC, 1 - cur);

        const __half* sA  = smem + cur * GSTAGE;
        const __half* sBh = sA + GARR;
        const __half* sBl = sBh + GARR;

#pragma unroll
        for (int ks = 0; ks < KC; ks += 16) {
            u32 af[2][4];
#pragma unroll
            for (int am = 0; am < 2; am++) {
                const int r0 = wm + am * 16 + g;
                af[am][0] = *(const u32*)&sA[(r0    ) * SSTR + ks + 2 * t];
                af[am][1] = *(const u32*)&sA[(r0 + 8) * SSTR + ks + 2 * t];
                af[am][2] = *(const u32*)&sA[(r0    ) * SSTR + ks + 2 * t + 8];
                af[am][3] = *(const u32*)&sA[(r0 + 8) * SSTR + ks + 2 * t + 8];
            }
            u32 bfh[8][2], bfl[8][2];
#pragma unroll
            for (int an = 0; an < 8; an++) {
                const int n = wn + an * 8 + g;
                bfh[an][0] = *(const u32*)&sBh[n * SSTR + ks + 2 * t];
                bfh[an][1] = *(const u32*)&sBh[n * SSTR + ks + 2 * t + 8];
                bfl[an][0] = *(const u32*)&sBl[n * SSTR + ks + 2 * t];
                bfl[an][1] = *(const u32*)&sBl[n * SSTR + ks + 2 * t + 8];
            }
#pragma unroll
            for (int am = 0; am < 2; am++)
#pragma unroll
                for (int an = 0; an < 8; an++) {
                    MMA_F16(acc[am][an], af[am], bfh[an]);
                    MMA_F16(acc[am][an], af[am], bfl[an]);
                }
        }
    }
}

// QKV: grid (M/128, NHEADS, 3), block 256. Writes split q/k/v in [b,h,s,d].
__global__ void __launch_bounds__(256) qkv_mma_kernel(
    const float* __restrict__ bQ, const float* __restrict__ bK, const float* __restrict__ bV)
{
    extern __shared__ __half smem[];
    const int mBase = blockIdx.x * 128;
    const int h     = blockIdx.y;
    const int which = blockIdx.z;
    const float* bias = ((which == 0) ? bQ : (which == 1) ? bK : bV) + h * DHEAD;
    __nv_bfloat16* dhi = (which == 0) ? gq_hi : (which == 1) ? gk_hi : gv_hi;
    __nv_bfloat16* dlo = (which == 0) ? gq_lo : (which == 1) ? gk_lo : gv_lo;
    const __half* Bh = gw16_hi + (size_t)(which * NHEADS + h) * DHEAD * DMODEL;
    const __half* Bl = gw16_lo + (size_t)(which * NHEADS + h) * DHEAD * DMODEL;

    float acc[2][8][4];
    gemm16_core(gx16, Bh, Bl, mBase, acc, smem);

    const int tid = threadIdx.x, wid = tid >> 5, lane = tid & 31;
    const int wm = (wid & 3) * 32, wn = (wid >> 2) * 64;
    const int g = lane >> 2, t = lane & 3;

#pragma unroll
    for (int am = 0; am < 2; am++)
#pragma unroll
        for (int an = 0; an < 8; an++) {
            const int col = wn + an * 8 + 2 * t;
            const float b0 = bias[col], b1 = bias[col + 1];
#pragma unroll
            for (int half = 0; half < 2; half++) {
                const int m = mBase + wm + am * 16 + g + 8 * half;
                const int bb = m >> 11;
                const int s  = m & (SEQLEN - 1);
                const size_t dst = (((size_t)(bb * NHEADS + h) * SEQLEN + s) * DHEAD + col);
                float v0 = acc[am][an][2 * half + 0] + b0;
                float v1 = acc[am][an][2 * half + 1] + b1;
                __nv_bfloat16 h0, l0, h1, l1;
                split1(v0, h0, l0); split1(v1, h1, l1);
                __nv_bfloat162 hp; hp.x = h0; hp.y = h1;
                __nv_bfloat162 lp; lp.x = l0; lp.y = l1;
                *(__nv_bfloat162*)&dhi[dst] = hp;
                *(__nv_bfloat162*)&dlo[dst] = lp;
            }
        }
}

// out proj: grid (M/128, DMODEL/128), block 256
__global__ void __launch_bounds__(256) out_mma_kernel(
    const float* __restrict__ bO, float* __restrict__ out)
{
    extern __shared__ __half smem[];
    const int mBase = blockIdx.x * 128;
    const int nBase = blockIdx.y * 128;
    float acc[2][8][4];
    gemm16_core(gz16,
                gwo16_hi + (size_t)nBase * DMODEL, gwo16_lo + (size_t)nBase * DMODEL,
                mBase, acc, smem);

    const int tid = threadIdx.x, wid = tid >> 5, lane = tid & 31;
    const int wm = (wid & 3) * 32, wn = (wid >> 2) * 64;
    const int g = lane >> 2, t = lane & 3;
    float* outBase = out + (size_t)mBase * DMODEL + nBase;
#pragma unroll
    for (int am = 0; am < 2; am++)
#pragma unroll
        for (int an = 0; an < 8; an++) {
            const int col = wn + an * 8 + 2 * t;
            const int r0 = wm + am * 16 + g;
            float b0 = bO[nBase + col], b1 = bO[nBase + col + 1];
            outBase[(size_t)r0 * DMODEL + col]           = acc[am][an][0] + b0;
            outBase[(size_t)r0 * DMODEL + col + 1]       = acc[am][an][1] + b1;
            outBase[(size_t)(r0 + 8) * DMODEL + col]     = acc[am][an][2] + b0;
            outBase[(size_t)(r0 + 8) * DMODEL + col + 1] = acc[am][an][3] + b1;
        }
}

// ---------------------------------------------------------------------------
// Tensor-core flash attention (bf16 3-term, unchanged core), z epilogue -> fp16.
// grid = (SEQLEN/128, NHEADS, BATCH), block = 256 (8 warps).
// ---------------------------------------------------------------------------
#define ASTR 136
#define AARR (64 * ASTR)
#define ASTAGE (4 * AARR)
#define AQ (128 * ASTR)
#define ATTN_SMEM ((2 * AQ + 2 * ASTAGE) * 2)

__global__ void __launch_bounds__(256, 1) attn_mma_kernel()
{
    const int qt = gridDim.x - 1 - blockIdx.x;
    const int h  = blockIdx.y;
    const int b  = blockIdx.z;
    const int qBase = qt * 128;

    extern __shared__ __nv_bfloat16 smem_a[];
    __nv_bfloat16* sQh = smem_a;
    __nv_bfloat16* sQl = sQh + AQ;
    __nv_bfloat16* kvs = sQl + AQ;

    const int tid = threadIdx.x;
    const int wid = tid >> 5;
    const int lane = tid & 31;
    const int g = lane >> 2;
    const int t = lane & 3;
    const int wrow = wid * 16;

    const size_t bh = (size_t)(b * NHEADS + h) * SEQLEN * DHEAD;
    const __nv_bfloat16* qh = gq_hi + bh;
    const __nv_bfloat16* ql = gq_lo + bh;
    const __nv_bfloat16* kh = gk_hi + bh;
    const __nv_bfloat16* kl = gk_lo + bh;
    const __nv_bfloat16* vh = gv_hi + bh;
    const __nv_bfloat16* vl = gv_lo + bh;

    const u32 kvbase = (u32)__cvta_generic_to_shared(kvs);

    auto issue_kv = [&](int kBase, int st) {
        const u32 b0 = kvbase + (u32)st * (ASTAGE * 2);
#pragma unroll
        for (int it = 0; it < 4; it++) {
            const int idx = tid + it * 256;
            const int r = idx >> 4;
            const int c = idx & 15;
            const u32 doff = (u32)(r * ASTR + c * 8) * 2;
            const size_t goff = (size_t)(kBase + r) * DHEAD + c * 8;
            cpa16(b0 + doff,                kh + goff);
            cpa16(b0 + AARR * 2 + doff,     kl + goff);
            cpa16(b0 + 2 * AARR * 2 + doff, vh + goff);
            cpa16(b0 + 3 * AARR * 2 + doff, vl + goff);
        }
        CP_COMMIT();
    };

    const int nkt = 2 * qt + 2;
    issue_kv(0, 0);

    for (int idx = tid; idx < 128 * 16; idx += 256) {
        const int r = idx >> 4, c8 = (idx & 15) * 8;
        *(uint4*)&sQh[r * ASTR + c8] = *(const uint4*)&qh[(size_t)(qBase + r) * DHEAD + c8];
        *(uint4*)&sQl[r * ASTR + c8] = *(const uint4*)&ql[(size_t)(qBase + r) * DHEAD + c8];
    }

    float o[16][4];
#pragma unroll
    for (int j = 0; j < 16; j++)
#pragma unroll
        for (int c = 0; c < 4; c++) o[j][c] = 0.f;
    float m0 = -1e30f, m1 = -1e30f, l0 = 0.f, l1 = 0.f;

    const float sl2e = 0.08838834764831845f * 1.4426950408889634f;

    for (int kt = 0; kt < nkt; kt++) {
        const int kBase = kt * 64;
        const int cur = kt & 1;
        CP_WAIT0();
        __syncthreads();
        if (kt + 1 < nkt) issue_kv((kt + 1) * 64, 1 - cur);

        if (kBase > qBase + wrow + 15) continue;

        const __nv_bfloat16* sKh = kvs + cur * ASTAGE;
        const __nv_bfloat16* sKl = sKh + AARR;
        const __nv_bfloat16* sVh = sKl + AARR;
        const __nv_bfloat16* sVl = sVh + AARR;

        float sacc[8][4];
#pragma unroll
        for (int an = 0; an < 8; an++)
#pragma unroll
            for (int c = 0; c < 4; c++) sacc[an][c] = 0.f;

#pragma unroll
        for (int ks = 0; ks < DHEAD; ks += 16) {
            u32 ah[4], al[4];
            const int r0 = wrow + g;
            ah[0] = *(const u32*)&sQh[(r0    ) * ASTR + ks + 2 * t];
            ah[1] = *(const u32*)&sQh[(r0 + 8) * ASTR + ks + 2 * t];
            ah[2] = *(const u32*)&sQh[(r0    ) * ASTR + ks + 2 * t + 8];
            ah[3] = *(const u32*)&sQh[(r0 + 8) * ASTR + ks + 2 * t + 8];
            al[0] = *(const u32*)&sQl[(r0    ) * ASTR + ks + 2 * t];
            al[1] = *(const u32*)&sQl[(r0 + 8) * ASTR + ks + 2 * t];
            al[2] = *(const u32*)&sQl[(r0    ) * ASTR + ks + 2 * t + 8];
            al[3] = *(const u32*)&sQl[(r0 + 8) * ASTR + ks + 2 * t + 8];
            u32 bh2[8][2], bl2[8][2];
#pragma unroll
            for (int an = 0; an < 8; an++) {
                const int n = an * 8 + g;
                bh2[an][0] = *(const u32*)&sKh[n * ASTR + ks + 2 * t];
                bh2[an][1] = *(const u32*)&sKh[n * ASTR + ks + 2 * t + 8];
                bl2[an][0] = *(const u32*)&sKl[n * ASTR + ks + 2 * t];
                bl2[an][1] = *(const u32*)&sKl[n * ASTR + ks + 2 * t + 8];
            }
#pragma unroll
            for (int an = 0; an < 8; an++) MMA_BF16(sacc[an], ah, bh2[an]);
#pragma unroll
            for (int an = 0; an < 8; an++) MMA_BF16(sacc[an], ah, bl2[an]);
#pragma unroll
            for (int an = 0; an < 8; an++) MMA_BF16(sacc[an], al, bh2[an]);
        }

        const int qr0 = qBase + wrow + g;
        const int qr1 = qr0 + 8;
#pragma unroll
        for (int an = 0; an < 8; an++) {
            const int c0 = kBase + an * 8 + 2 * t;
            sacc[an][0] = (c0     <= qr0) ? sacc[an][0] * sl2e : -1e30f;
            sacc[an][1] = (c0 + 1 <= qr0) ? sacc[an][1] * sl2e : -1e30f;
            sacc[an][2] = (c0     <= qr1) ? sacc[an][2] * sl2e : -1e30f;
            sacc[an][3] = (c0 + 1 <= qr1) ? sacc[an][3] * sl2e : -1e30f;
        }

        float mx0 = -1e30f, mx1 = -1e30f;
#pragma unroll
        for (int an = 0; an < 8; an++) {
            mx0 = fmaxf(mx0, fmaxf(sacc[an][0], sacc[an][1]));
            mx1 = fmaxf(mx1, fmaxf(sacc[an][2], sacc[an][3]));
        }
        mx0 = fmaxf(mx0, __shfl_xor_sync(0xffffffffu, mx0, 1));
        mx0 = fmaxf(mx0, __shfl_xor_sync(0xffffffffu, mx0, 2));
        mx1 = fmaxf(mx1, __shfl_xor_sync(0xffffffffu, mx1, 1));
        mx1 = fmaxf(mx1, __shfl_xor_sync(0xffffffffu, mx1, 2));

        const float mn0 = fmaxf(m0, mx0), mn1 = fmaxf(m1, mx1);
        const float al0 = ex2f(m0 - mn0), al1 = ex2f(m1 - mn1);
        m0 = mn0; m1 = mn1;

        float s0 = 0.f, s1 = 0.f;
#pragma unroll
        for (int an = 0; an < 8; an++) {
            sacc[an][0] = ex2f(sacc[an][0] - mn0);
            sacc[an][1] = ex2f(sacc[an][1] - mn0);
            sacc[an][2] = ex2f(sacc[an][2] - mn1);
            sacc[an][3] = ex2f(sacc[an][3] - mn1);
            s0 += sacc[an][0] + sacc[an][1];
            s1 += sacc[an][2] + sacc[an][3];
        }
        s0 += __shfl_xor_sync(0xffffffffu, s0, 1);
        s0 += __shfl_xor_sync(0xffffffffu, s0, 2);
        s1 += __shfl_xor_sync(0xffffffffu, s1, 1);
        s1 += __shfl_xor_sync(0xffffffffu, s1, 2);
        l0 = l0 * al0 + s0;
        l1 = l1 * al1 + s1;

#pragma unroll
        for (int j = 0; j < 16; j++) {
            o[j][0] *= al0; o[j][1] *= al0;
            o[j][2] *= al1; o[j][3] *= al1;
        }

        const u16* sVh16 = (const u16*)sVh;
        const u16* sVl16 = (const u16*)sVl;
#pragma unroll
        for (int jp = 0; jp < 4; jp++) {
            u32 aph[4], apl[4];
            {
                float p00 = sacc[2 * jp][0],     p01 = sacc[2 * jp][1];
                float p02 = sacc[2 * jp][2],     p03 = sacc[2 * jp][3];
                float p10 = sacc[2 * jp + 1][0], p11 = sacc[2 * jp + 1][1];
                float p12 = sacc[2 * jp + 1][2], p13 = sacc[2 * jp + 1][3];
                __nv_bfloat16 hh, ll;
                float h00, h01, h02, h03, h10, h11, h12, h13;
                split1(p00, hh, ll); h00 = __bfloat162float(hh);
                split1(p01, hh, ll); h01 = __bfloat162float(hh);
                split1(p02, hh, ll); h02 = __bfloat162float(hh);
                split1(p03, hh, ll); h03 = __bfloat162float(hh);
                split1(p10, hh, ll); h10 = __bfloat162float(hh);
                split1(p11, hh, ll); h11 = __bfloat162float(hh);
                split1(p12, hh, ll); h12 = __bfloat162float(hh);
                split1(p13, hh, ll); h13 = __bfloat162float(hh);
                aph[0] = pack2bf(h00, h01);
                aph[1] = pack2bf(h02, h03);
                aph[2] = pack2bf(h10, h11);
                aph[3] = pack2bf(h12, h13);
                apl[0] = pack2bf(p00 - h00, p01 - h01);
                apl[1] = pack2bf(p02 - h02, p03 - h03);
                apl[2] = pack2bf(p10 - h10, p11 - h11);
                apl[3] = pack2bf(p12 - h12, p13 - h13);
            }
            const int ks = 16 * jp;
#pragma unroll
            for (int anp = 0; anp < 2; anp++) {
                u32 vbh[8][2], vbl[8][2];
#pragma unroll
                for (int aj = 0; aj < 8; aj++) {
                    const int n = (anp * 8 + aj) * 8 + g;
                    u32 v0 = sVh16[(ks + 2 * t)     * ASTR + n];
                    u32 v1 = sVh16[(ks + 2 * t + 1) * ASTR + n];
                    u32 v8 = sVh16[(ks + 2 * t + 8) * ASTR + n];
                    u32 v9 = sVh16[(ks + 2 * t + 9) * ASTR + n];
                    vbh[aj][0] = v0 | (v1 << 16);
                    vbh[aj][1] = v8 | (v9 << 16);
                    v0 = sVl16[(ks + 2 * t)     * ASTR + n];
                    v1 = sVl16[(ks + 2 * t + 1) * ASTR + n];
                    v8 = sVl16[(ks + 2 * t + 8) * ASTR + n];
                    v9 = sVl16[(ks + 2 * t + 9) * ASTR + n];
                    vbl[aj][0] = v0 | (v1 << 16);
                    vbl[aj][1] = v8 | (v9 << 16);
                }
#pragma unroll
                for (int aj = 0; aj < 8; aj++) MMA_BF16(o[anp * 8 + aj], aph, vbh[aj]);
#pragma unroll
                for (int aj = 0; aj < 8; aj++) MMA_BF16(o[anp * 8 + aj], aph, vbl[aj]);
#pragma unroll
                for (int aj = 0; aj < 8; aj++) MMA_BF16(o[anp * 8 + aj], apl, vbh[aj]);
            }
        }
    }

    // epilogue: z = O / l -> fp16 single
    const float inv0 = 1.f / l0;
    const float inv1 = 1.f / l1;
    const int r0 = qBase + wrow + g;
#pragma unroll
    for (int an = 0; an < 16; an++) {
        const int col = an * 8 + 2 * t;
#pragma unroll
        for (int half = 0; half < 2; half++) {
            const int row = r0 + 8 * half;
            const float inv = half ? inv1 : inv0;
            float z0 = o[an][2 * half + 0] * inv;
            float z1 = o[an][2 * half + 1] * inv;
            __half2 zp; zp.x = __float2half(z0); zp.y = __float2half(z1);
            const size_t dst = ((size_t)(b * SEQLEN + row) * DMODEL + h * DHEAD + col);
            *(__half2*)&gz16[dst] = zp;
        }
    }
}

// ---------------------------------------------------------------------------
// Launch
// ---------------------------------------------------------------------------
extern "C" void kernel_launch(void* const* d_in, const int* in_sizes, int n_in,
                              void* d_out, int out_size)
{
    const float* x  = (const float*)d_in[0];
    const float* Wq = (const float*)d_in[1];
    const float* Wk = (const float*)d_in[2];
    const float* Wv = (const float*)d_in[3];
    const float* Wo = (const float*)d_in[4];
    const float* bQ = (const float*)d_in[5];
    const float* bK = (const float*)d_in[6];
    const float* bV = (const float*)d_in[7];
    const float* bO = (const float*)d_in[8];
    float* out = (float*)d_out;

    static bool attr_set = false;
    if (!attr_set) {
        cudaFuncSetAttribute(qkv_mma_kernel, cudaFuncAttributeMaxDynamicSharedMemorySize, GEMM_SMEM);
        cudaFuncSetAttribute(out_mma_kernel, cudaFuncAttributeMaxDynamicSharedMemorySize, GEMM_SMEM);
        cudaFuncSetAttribute(attn_mma_kernel, cudaFuncAttributeMaxDynamicSharedMemorySize, ATTN_SMEM);
        attr_set = true;
    }

    // 0) split/transposes (x -> fp16; weights -> fp16 hi/lo)
    split_x_kernel<<<(MTOT * DMODEL / 2) / 256, 256>>>(x);
    split_w_kernel<<<dim3(DMODEL / 32, DHEAD / 32, 3 * NHEADS), dim3(32, 8)>>>(Wq, Wk, Wv);
    split_wo_kernel<<<dim3(DMODEL / 32, DMODEL / 32), dim3(32, 8)>>>(Wo);

    // 1) QKV projections (fp16 2-term, 2 CTAs/SM)
    qkv_mma_kernel<<<dim3(MTOT / 128, NHEADS, 3), 256, GEMM_SMEM>>>(bQ, bK, bV);

    // 2) tensor-core flash attention (bf16 3-term)
    attn_mma_kernel<<<dim3(SEQLEN / 128, NHEADS, BATCH), 256, ATTN_SMEM>>>();

    // 3) output projection (fp16 2-term)
    out_mma_kernel<<<dim3(MTOT / 128, DMODEL / 128), 256, GEMM_SMEM>>>(bO, out);

    (void)in_sizes; (void)n_in; (void)out_size;
}

// round 15
// speedup vs baseline: 1.3131x; 1.0059x over previous
#include <cuda_runtime.h>
#include <cuda_bf16.h>
#include <cuda_fp16.h>
#include <math.h>

// Problem constants
#define BATCH   2
#define SEQLEN  2048
#define DMODEL  2048
#define NHEADS  16
#define DHEAD   128
#define MTOT    (BATCH * SEQLEN)      // 4096

typedef unsigned int u32;
typedef unsigned short u16;

// ---- fp16 split helper: v = hi + lo, residual ~2^-22
__device__ __forceinline__ void split1h(float v, __half& h, __half& l) {
    h = __float2half(v);
    l = __float2half(v - __half2float(h));
}
__device__ __forceinline__ u32 pack2h(float lo, float hi) {
    u32 r; asm("cvt.rn.f16x2.f32 %0, %1, %2;" : "=r"(r) : "f"(hi), "f"(lo)); return r;
}
__device__ __forceinline__ float ex2f(float x) {
    float y; asm("ex2.approx.f32 %0, %1;" : "=f"(y) : "f"(x)); return y;
}
// ---- cp.async helpers (16B; smem dst MUST be 16B-aligned: row pitch % 16B == 0)
__device__ __forceinline__ void cpa16(u32 dst_smem, const void* src) {
    asm volatile("cp.async.cg.shared.global [%0], [%1], 16;" :: "r"(dst_smem), "l"(src));
}
#define CP_COMMIT() asm volatile("cp.async.commit_group;")
#define CP_WAIT0()  asm volatile("cp.async.wait_group 0;")

// ---- scratch (device globals; device-side refs only)
__device__ __half gx16[(size_t)MTOT * DMODEL];          // x as fp16
__device__ __half gq16[(size_t)MTOT * DMODEL];          // q single fp16
__device__ __half gk16_hi[(size_t)MTOT * DMODEL];
__device__ __half gk16_lo[(size_t)MTOT * DMODEL];
__device__ __half gv16_hi[(size_t)MTOT * DMODEL];
__device__ __half gv16_lo[(size_t)MTOT * DMODEL];
__device__ __half gz16[(size_t)MTOT * DMODEL];          // z as fp16
// QKV weights transposed per head, fp16 split: [which][h][n(128)][k(2048)]
__device__ __half gw16_hi[(size_t)3 * NHEADS * DHEAD * DMODEL];
__device__ __half gw16_lo[(size_t)3 * NHEADS * DHEAD * DMODEL];
// W_O transposed, fp16 split: [n(2048)][k(2048)]
__device__ __half gwo16_hi[(size_t)DMODEL * DMODEL];
__device__ __half gwo16_lo[(size_t)DMODEL * DMODEL];

// ---------------------------------------------------------------------------
// Prep kernels
// ---------------------------------------------------------------------------
__global__ void __launch_bounds__(256) split_x_kernel(const float* __restrict__ x)
{
    size_t i = (size_t)blockIdx.x * blockDim.x + threadIdx.x;   // pair index
    float2 v = ((const float2*)x)[i];
    __half2 hp; hp.x = __float2half(v.x); hp.y = __float2half(v.y);
    ((__half2*)gx16)[i] = hp;
}

__global__ void split_w_kernel(const float* __restrict__ Wq,
                               const float* __restrict__ Wk,
                               const float* __restrict__ Wv)
{
    const int which = blockIdx.z / NHEADS;
    const int h     = blockIdx.z % NHEADS;
    const float* W = ((which == 0) ? Wq : (which == 1) ? Wk : Wv)
                     + (size_t)h * DMODEL * DHEAD;
    const int k0 = blockIdx.x * 32;
    const int n0 = blockIdx.y * 32;

    __shared__ float tile[32][33];
    const int tx = threadIdx.x, ty = threadIdx.y;
#pragma unroll
    for (int r = 0; r < 4; r++)
        tile[ty + 8 * r][tx] = W[(size_t)(k0 + ty + 8 * r) * DHEAD + n0 + tx];
    __syncthreads();
    const size_t base = ((size_t)(which * NHEADS + h) * DHEAD);
#pragma unroll
    for (int r = 0; r < 4; r++) {
        float v = tile[tx][ty + 8 * r];
        __half hh, ll; split1h(v, hh, ll);
        size_t idx = (base + n0 + ty + 8 * r) * DMODEL + k0 + tx;
        gw16_hi[idx] = hh; gw16_lo[idx] = ll;
    }
}

__global__ void split_wo_kernel(const float* __restrict__ Wo)
{
    const int k0 = blockIdx.x * 32;
    const int n0 = blockIdx.y * 32;
    __shared__ float tile[32][33];
    const int tx = threadIdx.x, ty = threadIdx.y;
#pragma unroll
    for (int r = 0; r < 4; r++)
        tile[ty + 8 * r][tx] = Wo[(size_t)(k0 + ty + 8 * r) * DMODEL + n0 + tx];
    __syncthreads();
#pragma unroll
    for (int r = 0; r < 4; r++) {
        float v = tile[tx][ty + 8 * r];
        __half hh, ll; split1h(v, hh, ll);
        size_t idx = (size_t)(n0 + ty + 8 * r) * DMODEL + k0 + tx;
        gwo16_hi[idx] = hh; gwo16_lo[idx] = ll;
    }
}

// ---------------------------------------------------------------------------
// fp16 2-term GEMM core: C = A16·Bh + A16·Bl (error only from A rounding).
// cp.async 2-stage, one sync/iter, 60 KB smem, 2 CTAs/SM.
// Block 256 thr (8 warps, 4x2), tile 128x128, K step 32.
// ---------------------------------------------------------------------------
#define KC   32
#define SSTR 40
#define GARR  (128 * SSTR)          // elems per array per stage
#define GSTAGE (3 * GARR)           // elems per stage (A16, Bh, Bl)
#define GEMM_SMEM (2 * GSTAGE * 2)  // 61440 bytes

#define MMA_F16(c, a, b) \
    asm volatile("mma.sync.aligned.m16n8k16.row.col.f32.f16.f16.f32 " \
        "{%0,%1,%2,%3}, {%4,%5,%6,%7}, {%8,%9}, {%0,%1,%2,%3};" \
        : "+f"((c)[0]), "+f"((c)[1]), "+f"((c)[2]), "+f"((c)[3]) \
        : "r"((a)[0]), "r"((a)[1]), "r"((a)[2]), "r"((a)[3]), \
          "r"((b)[0]), "r"((b)[1]))

__device__ __forceinline__ void gemm16_core(
    const __half* __restrict__ A16,
    const __half* __restrict__ Bh, const __half* __restrict__ Bl,
    int mBase, float acc[2][8][4], __half* smem)
{
    const int tid  = threadIdx.x;
    const int wid  = tid >> 5;
    const int lane = tid & 31;
    const int wm = (wid & 3) * 32;
    const int wn = (wid >> 2) * 64;
    const int g = lane >> 2;
    const int t = lane & 3;

    const u32 sbase = (u32)__cvta_generic_to_shared(smem);

#pragma unroll
    for (int am = 0; am < 2; am++)
#pragma unroll
        for (int an = 0; an < 8; an++)
#pragma unroll
            for (int c = 0; c < 4; c++) acc[am][an][c] = 0.f;

    auto issue_tile = [&](int k0, int st) {
        const u32 b0 = sbase + (u32)st * (GSTAGE * 2);
#pragma unroll
        for (int it = 0; it < 2; it++) {
            const int idx = tid + it * 256;      // 0..511
            const int r = idx >> 2;
            const int c = idx & 3;
            const u32 doff = (u32)(r * SSTR + c * 8) * 2;
            const size_t aoff = (size_t)(mBase + r) * DMODEL + k0 + c * 8;
            const size_t boff = (size_t)r * DMODEL + k0 + c * 8;
            cpa16(b0 + doff,                 A16 + aoff);
            cpa16(b0 + GARR * 2 + doff,      Bh + boff);
            cpa16(b0 + 2 * GARR * 2 + doff,  Bl + boff);
        }
        CP_COMMIT();
    };

    const int NKT = DMODEL / KC;   // 64
    issue_tile(0, 0);

    for (int kt = 0; kt < NKT; kt++) {
        const int cur = kt & 1;
        CP_WAIT0();
        __syncthreads();
        if (kt + 1 < NKT) issue_tile((kt + 1) * KC, 1 - cur);

        const __half* sA  = smem + cur * GSTAGE;
        const __half* sBh = sA + GARR;
        const __half* sBl = sBh + GARR;

#pragma unroll
        for (int ks = 0; ks < KC; ks += 16) {
            u32 af[2][4];
#pragma unroll
            for (int am = 0; am < 2; am++) {
                const int r0 = wm + am * 16 + g;
                af[am][0] = *(const u32*)&sA[(r0    ) * SSTR + ks + 2 * t];
                af[am][1] = *(const u32*)&sA[(r0 + 8) * SSTR + ks + 2 * t];
                af[am][2] = *(const u32*)&sA[(r0    ) * SSTR + ks + 2 * t + 8];
                af[am][3] = *(const u32*)&sA[(r0 + 8) * SSTR + ks + 2 * t + 8];
            }
            u32 bfh[8][2], bfl[8][2];
#pragma unroll
            for (int an = 0; an < 8; an++) {
                const int n = wn + an * 8 + g;
                bfh[an][0] = *(const u32*)&sBh[n * SSTR + ks + 2 * t];
                bfh[an][1] = *(const u32*)&sBh[n * SSTR + ks + 2 * t + 8];
                bfl[an][0] = *(const u32*)&sBl[n * SSTR + ks + 2 * t];
                bfl[an][1] = *(const u32*)&sBl[n * SSTR + ks + 2 * t + 8];
            }
#pragma unroll
            for (int am = 0; am < 2; am++)
#pragma unroll
                for (int an = 0; an < 8; an++) {
                    MMA_F16(acc[am][an], af[am], bfh[an]);
                    MMA_F16(acc[am][an], af[am], bfl[an]);
                }
        }
    }
}

// QKV: grid (M/128, NHEADS, 3), block 256.
// q -> single fp16 [b,h,s,d]; k,v -> fp16 hi/lo [b,h,s,d].
__global__ void __launch_bounds__(256) qkv_mma_kernel(
    const float* __restrict__ bQ, const float* __restrict__ bK, const float* __restrict__ bV)
{
    extern __shared__ __half smem[];
    const int mBase = blockIdx.x * 128;
    const int h     = blockIdx.y;
    const int which = blockIdx.z;
    const float* bias = ((which == 0) ? bQ : (which == 1) ? bK : bV) + h * DHEAD;
    const __half* Bh = gw16_hi + (size_t)(which * NHEADS + h) * DHEAD * DMODEL;
    const __half* Bl = gw16_lo + (size_t)(which * NHEADS + h) * DHEAD * DMODEL;

    float acc[2][8][4];
    gemm16_core(gx16, Bh, Bl, mBase, acc, smem);

    const int tid = threadIdx.x, wid = tid >> 5, lane = tid & 31;
    const int wm = (wid & 3) * 32, wn = (wid >> 2) * 64;
    const int g = lane >> 2, t = lane & 3;

    __half* dhi = (which == 1) ? gk16_hi : gv16_hi;
    __half* dlo = (which == 1) ? gk16_lo : gv16_lo;

#pragma unroll
    for (int am = 0; am < 2; am++)
#pragma unroll
        for (int an = 0; an < 8; an++) {
            const int col = wn + an * 8 + 2 * t;
            const float b0 = bias[col], b1 = bias[col + 1];
#pragma unroll
            for (int half = 0; half < 2; half++) {
                const int m = mBase + wm + am * 16 + g + 8 * half;
                const int bb = m >> 11;
                const int s  = m & (SEQLEN - 1);
                const size_t dst = (((size_t)(bb * NHEADS + h) * SEQLEN + s) * DHEAD + col);
                float v0 = acc[am][an][2 * half + 0] + b0;
                float v1 = acc[am][an][2 * half + 1] + b1;
                if (which == 0) {
                    __half2 qp; qp.x = __float2half(v0); qp.y = __float2half(v1);
                    *(__half2*)&gq16[dst] = qp;
                } else {
                    __half h0, l0, h1, l1;
                    split1h(v0, h0, l0); split1h(v1, h1, l1);
                    __half2 hp; hp.x = h0; hp.y = h1;
                    __half2 lp; lp.x = l0; lp.y = l1;
                    *(__half2*)&dhi[dst] = hp;
                    *(__half2*)&dlo[dst] = lp;
                }
            }
        }
}

// out proj: grid (M/128, DMODEL/128), block 256
__global__ void __launch_bounds__(256) out_mma_kernel(
    const float* __restrict__ bO, float* __restrict__ out)
{
    extern __shared__ __half smem[];
    const int mBase = blockIdx.x * 128;
    const int nBase = blockIdx.y * 128;
    float acc[2][8][4];
    gemm16_core(gz16,
                gwo16_hi + (size_t)nBase * DMODEL, gwo16_lo + (size_t)nBase * DMODEL,
                mBase, acc, smem);

    const int tid = threadIdx.x, wid = tid >> 5, lane = tid & 31;
    const int wm = (wid & 3) * 32, wn = (wid >> 2) * 64;
    const int g = lane >> 2, t = lane & 3;
    float* outBase = out + (size_t)mBase * DMODEL + nBase;
#pragma unroll
    for (int am = 0; am < 2; am++)
#pragma unroll
        for (int an = 0; an < 8; an++) {
            const int col = wn + an * 8 + 2 * t;
            const int r0 = wm + am * 16 + g;
            float b0 = bO[nBase + col], b1 = bO[nBase + col + 1];
            outBase[(size_t)r0 * DMODEL + col]           = acc[am][an][0] + b0;
            outBase[(size_t)r0 * DMODEL + col + 1]       = acc[am][an][1] + b1;
            outBase[(size_t)(r0 + 8) * DMODEL + col]     = acc[am][an][2] + b0;
            outBase[(size_t)(r0 + 8) * DMODEL + col + 1] = acc[am][an][3] + b1;
        }
}

// ---------------------------------------------------------------------------
// fp16 2-term flash attention:
//   S = Q16·Kh + Q16·Kl ;  O = P16·Vh + P16·Vl.
// cp.async 2-stage K/V pipeline, one sync/iter.
// grid = (SEQLEN/128, NHEADS, BATCH), block = 256 (8 warps).
// ---------------------------------------------------------------------------
#define ASTR 136
#define AARR (64 * ASTR)
#define ASTAGE (4 * AARR)           // kh, kl, vh, vl
#define AQ (128 * ASTR)
#define ATTN_SMEM ((AQ + 2 * ASTAGE) * 2)

__global__ void __launch_bounds__(256, 1) attn_mma_kernel()
{
    const int qt = gridDim.x - 1 - blockIdx.x;
    const int h  = blockIdx.y;
    const int b  = blockIdx.z;
    const int qBase = qt * 128;

    extern __shared__ __half smem_a[];
    __half* sQ  = smem_a;          // [128][ASTR]
    __half* kvs = sQ + AQ;         // 2 stages x [4][64][ASTR]

    const int tid = threadIdx.x;
    const int wid = tid >> 5;
    const int lane = tid & 31;
    const int g = lane >> 2;
    const int t = lane & 3;
    const int wrow = wid * 16;

    const size_t bh = (size_t)(b * NHEADS + h) * SEQLEN * DHEAD;
    const __half* q  = gq16 + bh;
    const __half* kh = gk16_hi + bh;
    const __half* kl = gk16_lo + bh;
    const __half* vh = gv16_hi + bh;
    const __half* vl = gv16_lo + bh;

    const u32 kvbase = (u32)__cvta_generic_to_shared(kvs);

    auto issue_kv = [&](int kBase, int st) {
        const u32 b0 = kvbase + (u32)st * (ASTAGE * 2);
#pragma unroll
        for (int it = 0; it < 4; it++) {
            const int idx = tid + it * 256;
            const int r = idx >> 4;
            const int c = idx & 15;
            const u32 doff = (u32)(r * ASTR + c * 8) * 2;
            const size_t goff = (size_t)(kBase + r) * DHEAD + c * 8;
            cpa16(b0 + doff,                kh + goff);
            cpa16(b0 + AARR * 2 + doff,     kl + goff);
            cpa16(b0 + 2 * AARR * 2 + doff, vh + goff);
            cpa16(b0 + 3 * AARR * 2 + doff, vl + goff);
        }
        CP_COMMIT();
    };

    const int nkt = 2 * qt + 2;
    issue_kv(0, 0);

    for (int idx = tid; idx < 128 * 16; idx += 256) {
        const int r = idx >> 4, c8 = (idx & 15) * 8;
        *(uint4*)&sQ[r * ASTR + c8] = *(const uint4*)&q[(size_t)(qBase + r) * DHEAD + c8];
    }

    float o[16][4];
#pragma unroll
    for (int j = 0; j < 16; j++)
#pragma unroll
        for (int c = 0; c < 4; c++) o[j][c] = 0.f;
    float m0 = -1e30f, m1 = -1e30f, l0 = 0.f, l1 = 0.f;

    const float sl2e = 0.08838834764831845f * 1.4426950408889634f;

    for (int kt = 0; kt < nkt; kt++) {
        const int kBase = kt * 64;
        const int cur = kt & 1;
        CP_WAIT0();
        __syncthreads();
        if (kt + 1 < nkt) issue_kv((kt + 1) * 64, 1 - cur);

        if (kBase > qBase + wrow + 15) continue;

        const __half* sKh = kvs + cur * ASTAGE;
        const __half* sKl = sKh + AARR;
        const __half* sVh = sKl + AARR;
        const __half* sVl = sVh + AARR;

        float sacc[8][4];
#pragma unroll
        for (int an = 0; an < 8; an++)
#pragma unroll
            for (int c = 0; c < 4; c++) sacc[an][c] = 0.f;

#pragma unroll
        for (int ks = 0; ks < DHEAD; ks += 16) {
            u32 aq[4];
            const int r0 = wrow + g;
            aq[0] = *(const u32*)&sQ[(r0    ) * ASTR + ks + 2 * t];
            aq[1] = *(const u32*)&sQ[(r0 + 8) * ASTR + ks + 2 * t];
            aq[2] = *(const u32*)&sQ[(r0    ) * ASTR + ks + 2 * t + 8];
            aq[3] = *(const u32*)&sQ[(r0 + 8) * ASTR + ks + 2 * t + 8];
            u32 bh2[8][2], bl2[8][2];
#pragma unroll
            for (int an = 0; an < 8; an++) {
                const int n = an * 8 + g;
                bh2[an][0] = *(const u32*)&sKh[n * ASTR + ks + 2 * t];
                bh2[an][1] = *(const u32*)&sKh[n * ASTR + ks + 2 * t + 8];
                bl2[an][0] = *(const u32*)&sKl[n * ASTR + ks + 2 * t];
                bl2[an][1] = *(const u32*)&sKl[n * ASTR + ks + 2 * t + 8];
            }
#pragma unroll
            for (int an = 0; an < 8; an++) MMA_F16(sacc[an], aq, bh2[an]);
#pragma unroll
            for (int an = 0; an < 8; an++) MMA_F16(sacc[an], aq, bl2[an]);
        }

        const int qr0 = qBase + wrow + g;
        const int qr1 = qr0 + 8;
#pragma unroll
        for (int an = 0; an < 8; an++) {
            const int c0 = kBase + an * 8 + 2 * t;
            sacc[an][0] = (c0     <= qr0) ? sacc[an][0] * sl2e : -1e30f;
            sacc[an][1] = (c0 + 1 <= qr0) ? sacc[an][1] * sl2e : -1e30f;
            sacc[an][2] = (c0     <= qr1) ? sacc[an][2] * sl2e : -1e30f;
            sacc[an][3] = (c0 + 1 <= qr1) ? sacc[an][3] * sl2e : -1e30f;
        }

        float mx0 = -1e30f, mx1 = -1e30f;
#pragma unroll
        for (int an = 0; an < 8; an++) {
            mx0 = fmaxf(mx0, fmaxf(sacc[an][0], sacc[an][1]));
            mx1 = fmaxf(mx1, fmaxf(sacc[an][2], sacc[an][3]));
        }
        mx0 = fmaxf(mx0, __shfl_xor_sync(0xffffffffu, mx0, 1));
        mx0 = fmaxf(mx0, __shfl_xor_sync(0xffffffffu, mx0, 2));
        mx1 = fmaxf(mx1, __shfl_xor_sync(0xffffffffu, mx1, 1));
        mx1 = fmaxf(mx1, __shfl_xor_sync(0xffffffffu, mx1, 2));

        const float mn0 = fmaxf(m0, mx0), mn1 = fmaxf(m1, mx1);
        const float al0 = ex2f(m0 - mn0), al1 = ex2f(m1 - mn1);
        m0 = mn0; m1 = mn1;

        float s0 = 0.f, s1 = 0.f;
#pragma unroll
        for (int an = 0; an < 8; an++) {
            sacc[an][0] = ex2f(sacc[an][0] - mn0);
            sacc[an][1] = ex2f(sacc[an][1] - mn0);
            sacc[an][2] = ex2f(sacc[an][2] - mn1);
            sacc[an][3] = ex2f(sacc[an][3] - mn1);
            s0 += sacc[an][0] + sacc[an][1];
            s1 += sacc[an][2] + sacc[an][3];
        }
        s0 += __shfl_xor_sync(0xffffffffu, s0, 1);
        s0 += __shfl_xor_sync(0xffffffffu, s0, 2);
        s1 += __shfl_xor_sync(0xffffffffu, s1, 1);
        s1 += __shfl_xor_sync(0xffffffffu, s1, 2);
        l0 = l0 * al0 + s0;
        l1 = l1 * al1 + s1;

#pragma unroll
        for (int j = 0; j < 16; j++) {
            o[j][0] *= al0; o[j][1] *= al0;
            o[j][2] *= al1; o[j][3] *= al1;
        }

        const u16* sVh16 = (const u16*)sVh;
        const u16* sVl16 = (const u16*)sVl;
#pragma unroll
        for (int jp = 0; jp < 4; jp++) {
            u32 ap[4];
            ap[0] = pack2h(sacc[2 * jp][0],     sacc[2 * jp][1]);
            ap[1] = pack2h(sacc[2 * jp][2],     sacc[2 * jp][3]);
            ap[2] = pack2h(sacc[2 * jp + 1][0], sacc[2 * jp + 1][1]);
            ap[3] = pack2h(sacc[2 * jp + 1][2], sacc[2 * jp + 1][3]);
            const int ks = 16 * jp;
#pragma unroll
            for (int anp = 0; anp < 2; anp++) {
                u32 vbh[8][2], vbl[8][2];
#pragma unroll
                for (int aj = 0; aj < 8; aj++) {
                    const int n = (anp * 8 + aj) * 8 + g;
                    u32 v0 = sVh16[(ks + 2 * t)     * ASTR + n];
                    u32 v1 = sVh16[(ks + 2 * t + 1) * ASTR + n];
                    u32 v8 = sVh16[(ks + 2 * t + 8) * ASTR + n];
                    u32 v9 = sVh16[(ks + 2 * t + 9) * ASTR + n];
                    vbh[aj][0] = v0 | (v1 << 16);
                    vbh[aj][1] = v8 | (v9 << 16);
                    v0 = sVl16[(ks + 2 * t)     * ASTR + n];
                    v1 = sVl16[(ks + 2 * t + 1) * ASTR + n];
                    v8 = sVl16[(ks + 2 * t + 8) * ASTR + n];
                    v9 = sVl16[(ks + 2 * t + 9) * ASTR + n];
                    vbl[aj][0] = v0 | (v1 << 16);
                    vbl[aj][1] = v8 | (v9 << 16);
                }
#pragma unroll
                for (int aj = 0; aj < 8; aj++) MMA_F16(o[anp * 8 + aj], ap, vbh[aj]);
#pragma unroll
                for (int aj = 0; aj < 8; aj++) MMA_F16(o[anp * 8 + aj], ap, vbl[aj]);
            }
        }
    }

    // epilogue: z = O / l -> fp16 single
    const float inv0 = 1.f / l0;
    const float inv1 = 1.f / l1;
    const int r0 = qBase + wrow + g;
#pragma unroll
    for (int an = 0; an < 16; an++) {
        const int col = an * 8 + 2 * t;
#pragma unroll
        for (int half = 0; half < 2; half++) {
            const int row = r0 + 8 * half;
            const float inv = half ? inv1 : inv0;
            float z0 = o[an][2 * half + 0] * inv;
            float z1 = o[an][2 * half + 1] * inv;
            __half2 zp; zp.x = __float2half(z0); zp.y = __float2half(z1);
            const size_t dst = ((size_t)(b * SEQLEN + row) * DMODEL + h * DHEAD + col);
            *(__half2*)&gz16[dst] = zp;
        }
    }
}

// ---------------------------------------------------------------------------
// Launch
// ---------------------------------------------------------------------------
extern "C" void kernel_launch(void* const* d_in, const int* in_sizes, int n_in,
                              void* d_out, int out_size)
{
    const float* x  = (const float*)d_in[0];
    const float* Wq = (const float*)d_in[1];
    const float* Wk = (const float*)d_in[2];
    const float* Wv = (const float*)d_in[3];
    const float* Wo = (const float*)d_in[4];
    const float* bQ = (const float*)d_in[5];
    const float* bK = (const float*)d_in[6];
    const float* bV = (const float*)d_in[7];
    const float* bO = (const float*)d_in[8];
    float* out = (float*)d_out;

    static bool attr_set = false;
    if (!attr_set) {
        cudaFuncSetAttribute(qkv_mma_kernel, cudaFuncAttributeMaxDynamicSharedMemorySize, GEMM_SMEM);
        cudaFuncSetAttribute(out_mma_kernel, cudaFuncAttributeMaxDynamicSharedMemorySize, GEMM_SMEM);
        cudaFuncSetAttribute(attn_mma_kernel, cudaFuncAttributeMaxDynamicSharedMemorySize, ATTN_SMEM);
        attr_set = true;
    }

    // 0) splits (x -> fp16; weights -> fp16 hi/lo)
    split_x_kernel<<<(MTOT * DMODEL / 2) / 256, 256>>>(x);
    split_w_kernel<<<dim3(DMODEL / 32, DHEAD / 32, 3 * NHEADS), dim3(32, 8)>>>(Wq, Wk, Wv);
    split_wo_kernel<<<dim3(DMODEL / 32, DMODEL / 32), dim3(32, 8)>>>(Wo);

    // 1) QKV projections (fp16 2-term)
    qkv_mma_kernel<<<dim3(MTOT / 128, NHEADS, 3), 256, GEMM_SMEM>>>(bQ, bK, bV);

    // 2) fp16 2-term flash attention
    attn_mma_kernel<<<dim3(SEQLEN / 128, NHEADS, BATCH), 256, ATTN_SMEM>>>();

    // 3) output projection (fp16 2-term)
    out_mma_kernel<<<dim3(MTOT / 128, DMODEL / 128), 256, GEMM_SMEM>>>(bO, out);

    (void)in_sizes; (void)n_in; (void)out_size;
}

// round 16
// speedup vs baseline: 1.4224x; 1.0833x over previous
#include <cuda_runtime.h>
#include <cuda_bf16.h>
#include <cuda_fp16.h>
#include <math.h>

// Problem constants
#define BATCH   2
#define SEQLEN  2048
#define DMODEL  2048
#define NHEADS  16
#define DHEAD   128
#define MTOT    (BATCH * SEQLEN)      // 4096

typedef unsigned int u32;
typedef unsigned short u16;

// ---- fp16 split helper: v = hi + lo, residual ~2^-22
__device__ __forceinline__ void split1h(float v, __half& h, __half& l) {
    h = __float2half(v);
    l = __float2half(v - __half2float(h));
}
__device__ __forceinline__ u32 pack2h(float lo, float hi) {
    u32 r; asm("cvt.rn.f16x2.f32 %0, %1, %2;" : "=r"(r) : "f"(hi), "f"(lo)); return r;
}
__device__ __forceinline__ float ex2f(float x) {
    float y; asm("ex2.approx.f32 %0, %1;" : "=f"(y) : "f"(x)); return y;
}
// ---- cp.async helpers (16B; smem dst MUST be 16B-aligned: row pitch % 16B == 0)
__device__ __forceinline__ void cpa16(u32 dst_smem, const void* src) {
    asm volatile("cp.async.cg.shared.global [%0], [%1], 16;" :: "r"(dst_smem), "l"(src));
}
#define CP_COMMIT() asm volatile("cp.async.commit_group;")
#define CP_WAIT0()  asm volatile("cp.async.wait_group 0;")

// ---- scratch (device globals; device-side refs only)
__device__ __half gx16[(size_t)MTOT * DMODEL];          // x as fp16
__device__ __half gq16[(size_t)MTOT * DMODEL];          // q single fp16
__device__ __half gk16_hi[(size_t)MTOT * DMODEL];
__device__ __half gk16_lo[(size_t)MTOT * DMODEL];
__device__ __half gv16[(size_t)MTOT * DMODEL];          // v single fp16
__device__ __half gz16[(size_t)MTOT * DMODEL];          // z as fp16
// QKV weights transposed per head, fp16 split: [which][h][n(128)][k(2048)]
__device__ __half gw16_hi[(size_t)3 * NHEADS * DHEAD * DMODEL];
__device__ __half gw16_lo[(size_t)3 * NHEADS * DHEAD * DMODEL];
// W_O transposed, fp16 split: [n(2048)][k(2048)]
__device__ __half gwo16_hi[(size_t)DMODEL * DMODEL];
__device__ __half gwo16_lo[(size_t)DMODEL * DMODEL];

// ---------------------------------------------------------------------------
// Prep kernels
// ---------------------------------------------------------------------------
__global__ void __launch_bounds__(256) split_x_kernel(const float* __restrict__ x)
{
    size_t i = (size_t)blockIdx.x * blockDim.x + threadIdx.x;   // pair index
    float2 v = ((const float2*)x)[i];
    __half2 hp; hp.x = __float2half(v.x); hp.y = __float2half(v.y);
    ((__half2*)gx16)[i] = hp;
}

__global__ void split_w_kernel(const float* __restrict__ Wq,
                               const float* __restrict__ Wk,
                               const float* __restrict__ Wv)
{
    const int which = blockIdx.z / NHEADS;
    const int h     = blockIdx.z % NHEADS;
    const float* W = ((which == 0) ? Wq : (which == 1) ? Wk : Wv)
                     + (size_t)h * DMODEL * DHEAD;
    const int k0 = blockIdx.x * 32;
    const int n0 = blockIdx.y * 32;

    __shared__ float tile[32][33];
    const int tx = threadIdx.x, ty = threadIdx.y;
#pragma unroll
    for (int r = 0; r < 4; r++)
        tile[ty + 8 * r][tx] = W[(size_t)(k0 + ty + 8 * r) * DHEAD + n0 + tx];
    __syncthreads();
    const size_t base = ((size_t)(which * NHEADS + h) * DHEAD);
#pragma unroll
    for (int r = 0; r < 4; r++) {
        float v = tile[tx][ty + 8 * r];
        __half hh, ll; split1h(v, hh, ll);
        size_t idx = (base + n0 + ty + 8 * r) * DMODEL + k0 + tx;
        gw16_hi[idx] = hh; gw16_lo[idx] = ll;
    }
}

__global__ void split_wo_kernel(const float* __restrict__ Wo)
{
    const int k0 = blockIdx.x * 32;
    const int n0 = blockIdx.y * 32;
    __shared__ float tile[32][33];
    const int tx = threadIdx.x, ty = threadIdx.y;
#pragma unroll
    for (int r = 0; r < 4; r++)
        tile[ty + 8 * r][tx] = Wo[(size_t)(k0 + ty + 8 * r) * DMODEL + n0 + tx];
    __syncthreads();
#pragma unroll
    for (int r = 0; r < 4; r++) {
        float v = tile[tx][ty + 8 * r];
        __half hh, ll; split1h(v, hh, ll);
        size_t idx = (size_t)(n0 + ty + 8 * r) * DMODEL + k0 + tx;
        gwo16_hi[idx] = hh; gwo16_lo[idx] = ll;
    }
}

// ---------------------------------------------------------------------------
// fp16 2-term GEMM core: C = A16·Bh + A16·Bl (error only from A rounding).
// cp.async 2-stage, one sync/iter, 60 KB smem, 2 CTAs/SM.
// Block 256 thr (8 warps, 4x2), tile 128x128, K step 32.
// ---------------------------------------------------------------------------
#define KC   32
#define SSTR 40
#define GARR  (128 * SSTR)          // elems per array per stage
#define GSTAGE (3 * GARR)           // elems per stage (A16, Bh, Bl)
#define GEMM_SMEM (2 * GSTAGE * 2)  // 61440 bytes

#define MMA_F16(c, a, b) \
    asm volatile("mma.sync.aligned.m16n8k16.row.col.f32.f16.f16.f32 " \
        "{%0,%1,%2,%3}, {%4,%5,%6,%7}, {%8,%9}, {%0,%1,%2,%3};" \
        : "+f"((c)[0]), "+f"((c)[1]), "+f"((c)[2]), "+f"((c)[3]) \
        : "r"((a)[0]), "r"((a)[1]), "r"((a)[2]), "r"((a)[3]), \
          "r"((b)[0]), "r"((b)[1]))

__device__ __forceinline__ void gemm16_core(
    const __half* __restrict__ A16,
    const __half* __restrict__ Bh, const __half* __restrict__ Bl,
    int mBase, float acc[2][8][4], __half* smem)
{
    const int tid  = threadIdx.x;
    const int wid  = tid >> 5;
    const int lane = tid & 31;
    const int wm = (wid & 3) * 32;
    const int wn = (wid >> 2) * 64;
    const int g = lane >> 2;
    const int t = lane & 3;

    const u32 sbase = (u32)__cvta_generic_to_shared(smem);

#pragma unroll
    for (int am = 0; am < 2; am++)
#pragma unroll
        for (int an = 0; an < 8; an++)
#pragma unroll
            for (int c = 0; c < 4; c++) acc[am][an][c] = 0.f;

    auto issue_tile = [&](int k0, int st) {
        const u32 b0 = sbase + (u32)st * (GSTAGE * 2);
#pragma unroll
        for (int it = 0; it < 2; it++) {
            const int idx = tid + it * 256;      // 0..511
            const int r = idx >> 2;
            const int c = idx & 3;
            const u32 doff = (u32)(r * SSTR + c * 8) * 2;
            const size_t aoff = (size_t)(mBase + r) * DMODEL + k0 + c * 8;
            const size_t boff = (size_t)r * DMODEL + k0 + c * 8;
            cpa16(b0 + doff,                 A16 + aoff);
            cpa16(b0 + GARR * 2 + doff,      Bh + boff);
            cpa16(b0 + 2 * GARR * 2 + doff,  Bl + boff);
        }
        CP_COMMIT();
    };

    const int NKT = DMODEL / KC;   // 64
    issue_tile(0, 0);

    for (int kt = 0; kt < NKT; kt++) {
        const int cur = kt & 1;
        CP_WAIT0();
        __syncthreads();
        if (kt + 1 < NKT) issue_tile((kt + 1) * KC, 1 - cur);

        const __half* sA  = smem + cur * GSTAGE;
        const __half* sBh = sA + GARR;
        const __half* sBl = sBh + GARR;

#pragma unroll
        for (int ks = 0; ks < KC; ks += 16) {
            u32 af[2][4];
#pragma unroll
            for (int am = 0; am < 2; am++) {
                const int r0 = wm + am * 16 + g;
                af[am][0] = *(const u32*)&sA[(r0    ) * SSTR + ks + 2 * t];
                af[am][1] = *(const u32*)&sA[(r0 + 8) * SSTR + ks + 2 * t];
                af[am][2] = *(const u32*)&sA[(r0    ) * SSTR + ks + 2 * t + 8];
                af[am][3] = *(const u32*)&sA[(r0 + 8) * SSTR + ks + 2 * t + 8];
            }
            u32 bfh[8][2], bfl[8][2];
#pragma unroll
            for (int an = 0; an < 8; an++) {
                const int n = wn + an * 8 + g;
                bfh[an][0] = *(const u32*)&sBh[n * SSTR + ks + 2 * t];
                bfh[an][1] = *(const u32*)&sBh[n * SSTR + ks + 2 * t + 8];
                bfl[an][0] = *(const u32*)&sBl[n * SSTR + ks + 2 * t];
                bfl[an][1] = *(const u32*)&sBl[n * SSTR + ks + 2 * t + 8];
            }
#pragma unroll
            for (int am = 0; am < 2; am++)
#pragma unroll
                for (int an = 0; an < 8; an++) {
                    MMA_F16(acc[am][an], af[am], bfh[an]);
                    MMA_F16(acc[am][an], af[am], bfl[an]);
                }
        }
    }
}

// q / v projection: grid (M/128, NHEADS, 2). z=0 -> q, z=1 -> v.
// Writes single fp16 in [b,h,s,d]. Non-divergent epilogue.
__global__ void __launch_bounds__(256) proj_single_kernel(
    const float* __restrict__ bQ, const float* __restrict__ bV)
{
    extern __shared__ __half smem[];
    const int mBase = blockIdx.x * 128;
    const int h     = blockIdx.y;
    const int which = blockIdx.z ? 2 : 0;      // 0 -> q, 2 -> v
    const float* bias = (blockIdx.z ? bV : bQ) + h * DHEAD;
    __half* dst16 = blockIdx.z ? gv16 : gq16;
    const __half* Bh = gw16_hi + (size_t)(which * NHEADS + h) * DHEAD * DMODEL;
    const __half* Bl = gw16_lo + (size_t)(which * NHEADS + h) * DHEAD * DMODEL;

    float acc[2][8][4];
    gemm16_core(gx16, Bh, Bl, mBase, acc, smem);

    const int tid = threadIdx.x, wid = tid >> 5, lane = tid & 31;
    const int wm = (wid & 3) * 32, wn = (wid >> 2) * 64;
    const int g = lane >> 2, t = lane & 3;

#pragma unroll
    for (int am = 0; am < 2; am++)
#pragma unroll
        for (int an = 0; an < 8; an++) {
            const int col = wn + an * 8 + 2 * t;
            const float b0 = bias[col], b1 = bias[col + 1];
#pragma unroll
            for (int half = 0; half < 2; half++) {
                const int m = mBase + wm + am * 16 + g + 8 * half;
                const int bb = m >> 11;
                const int s  = m & (SEQLEN - 1);
                const size_t dst = (((size_t)(bb * NHEADS + h) * SEQLEN + s) * DHEAD + col);
                float v0 = acc[am][an][2 * half + 0] + b0;
                float v1 = acc[am][an][2 * half + 1] + b1;
                __half2 p; p.x = __float2half(v0); p.y = __float2half(v1);
                *(__half2*)&dst16[dst] = p;
            }
        }
}

// k projection: grid (M/128, NHEADS). Writes fp16 hi/lo in [b,h,s,d].
__global__ void __launch_bounds__(256) proj_k_kernel(const float* __restrict__ bK)
{
    extern __shared__ __half smem[];
    const int mBase = blockIdx.x * 128;
    const int h     = blockIdx.y;
    const float* bias = bK + h * DHEAD;
    const __half* Bh = gw16_hi + (size_t)(1 * NHEADS + h) * DHEAD * DMODEL;
    const __half* Bl = gw16_lo + (size_t)(1 * NHEADS + h) * DHEAD * DMODEL;

    float acc[2][8][4];
    gemm16_core(gx16, Bh, Bl, mBase, acc, smem);

    const int tid = threadIdx.x, wid = tid >> 5, lane = tid & 31;
    const int wm = (wid & 3) * 32, wn = (wid >> 2) * 64;
    const int g = lane >> 2, t = lane & 3;

#pragma unroll
    for (int am = 0; am < 2; am++)
#pragma unroll
        for (int an = 0; an < 8; an++) {
            const int col = wn + an * 8 + 2 * t;
            const float b0 = bias[col], b1 = bias[col + 1];
#pragma unroll
            for (int half = 0; half < 2; half++) {
                const int m = mBase + wm + am * 16 + g + 8 * half;
                const int bb = m >> 11;
                const int s  = m & (SEQLEN - 1);
                const size_t dst = (((size_t)(bb * NHEADS + h) * SEQLEN + s) * DHEAD + col);
                float v0 = acc[am][an][2 * half + 0] + b0;
                float v1 = acc[am][an][2 * half + 1] + b1;
                __half h0, l0, h1, l1;
                split1h(v0, h0, l0); split1h(v1, h1, l1);
                __half2 hp; hp.x = h0; hp.y = h1;
                __half2 lp; lp.x = l0; lp.y = l1;
                *(__half2*)&gk16_hi[dst] = hp;
                *(__half2*)&gk16_lo[dst] = lp;
            }
        }
}

// out proj: grid (M/128, DMODEL/128), block 256
__global__ void __launch_bounds__(256) out_mma_kernel(
    const float* __restrict__ bO, float* __restrict__ out)
{
    extern __shared__ __half smem[];
    const int mBase = blockIdx.x * 128;
    const int nBase = blockIdx.y * 128;
    float acc[2][8][4];
    gemm16_core(gz16,
                gwo16_hi + (size_t)nBase * DMODEL, gwo16_lo + (size_t)nBase * DMODEL,
                mBase, acc, smem);

    const int tid = threadIdx.x, wid = tid >> 5, lane = tid & 31;
    const int wm = (wid & 3) * 32, wn = (wid >> 2) * 64;
    const int g = lane >> 2, t = lane & 3;
    float* outBase = out + (size_t)mBase * DMODEL + nBase;
#pragma unroll
    for (int am = 0; am < 2; am++)
#pragma unroll
        for (int an = 0; an < 8; an++) {
            const int col = wn + an * 8 + 2 * t;
            const int r0 = wm + am * 16 + g;
            float b0 = bO[nBase + col], b1 = bO[nBase + col + 1];
            outBase[(size_t)r0 * DMODEL + col]           = acc[am][an][0] + b0;
            outBase[(size_t)r0 * DMODEL + col + 1]       = acc[am][an][1] + b1;
            outBase[(size_t)(r0 + 8) * DMODEL + col]     = acc[am][an][2] + b0;
            outBase[(size_t)(r0 + 8) * DMODEL + col + 1] = acc[am][an][3] + b1;
        }
}

// ---------------------------------------------------------------------------
// fp16 flash attention:
//   S = Q16·Kh + Q16·Kl  (K 2-term);  O = P16·V16 (single term).
// cp.async 2-stage K/V pipeline (3 arrays), one sync/iter.
// grid = (SEQLEN/128, NHEADS, BATCH), block = 256 (8 warps).
// ---------------------------------------------------------------------------
#define ASTR 136
#define AARR (64 * ASTR)
#define ASTAGE (3 * AARR)           // kh, kl, v16
#define AQ (128 * ASTR)
#define ATTN_SMEM ((AQ + 2 * ASTAGE) * 2)

__global__ void __launch_bounds__(256, 1) attn_mma_kernel()
{
    const int qt = gridDim.x - 1 - blockIdx.x;
    const int h  = blockIdx.y;
    const int b  = blockIdx.z;
    const int qBase = qt * 128;

    extern __shared__ __half smem_a[];
    __half* sQ  = smem_a;          // [128][ASTR]
    __half* kvs = sQ + AQ;         // 2 stages x [3][64][ASTR]

    const int tid = threadIdx.x;
    const int wid = tid >> 5;
    const int lane = tid & 31;
    const int g = lane >> 2;
    const int t = lane & 3;
    const int wrow = wid * 16;

    const size_t bh = (size_t)(b * NHEADS + h) * SEQLEN * DHEAD;
    const __half* q  = gq16 + bh;
    const __half* kh = gk16_hi + bh;
    const __half* kl = gk16_lo + bh;
    const __half* v  = gv16 + bh;

    const u32 kvbase = (u32)__cvta_generic_to_shared(kvs);

    auto issue_kv = [&](int kBase, int st) {
        const u32 b0 = kvbase + (u32)st * (ASTAGE * 2);
#pragma unroll
        for (int it = 0; it < 4; it++) {
            const int idx = tid + it * 256;
            const int r = idx >> 4;
            const int c = idx & 15;
            const u32 doff = (u32)(r * ASTR + c * 8) * 2;
            const size_t goff = (size_t)(kBase + r) * DHEAD + c * 8;
            cpa16(b0 + doff,                kh + goff);
            cpa16(b0 + AARR * 2 + doff,     kl + goff);
            cpa16(b0 + 2 * AARR * 2 + doff, v + goff);
        }
        CP_COMMIT();
    };

    const int nkt = 2 * qt + 2;
    issue_kv(0, 0);

    for (int idx = tid; idx < 128 * 16; idx += 256) {
        const int r = idx >> 4, c8 = (idx & 15) * 8;
        *(uint4*)&sQ[r * ASTR + c8] = *(const uint4*)&q[(size_t)(qBase + r) * DHEAD + c8];
    }

    float o[16][4];
#pragma unroll
    for (int j = 0; j < 16; j++)
#pragma unroll
        for (int c = 0; c < 4; c++) o[j][c] = 0.f;
    float m0 = -1e30f, m1 = -1e30f, l0 = 0.f, l1 = 0.f;

    const float sl2e = 0.08838834764831845f * 1.4426950408889634f;

    for (int kt = 0; kt < nkt; kt++) {
        const int kBase = kt * 64;
        const int cur = kt & 1;
        CP_WAIT0();
        __syncthreads();
        if (kt + 1 < nkt) issue_kv((kt + 1) * 64, 1 - cur);

        if (kBase > qBase + wrow + 15) continue;

        const __half* sKh = kvs + cur * ASTAGE;
        const __half* sKl = sKh + AARR;
        const __half* sV  = sKl + AARR;

        float sacc[8][4];
#pragma unroll
        for (int an = 0; an < 8; an++)
#pragma unroll
            for (int c = 0; c < 4; c++) sacc[an][c] = 0.f;

#pragma unroll
        for (int ks = 0; ks < DHEAD; ks += 16) {
            u32 aq[4];
            const int r0 = wrow + g;
            aq[0] = *(const u32*)&sQ[(r0    ) * ASTR + ks + 2 * t];
            aq[1] = *(const u32*)&sQ[(r0 + 8) * ASTR + ks + 2 * t];
            aq[2] = *(const u32*)&sQ[(r0    ) * ASTR + ks + 2 * t + 8];
            aq[3] = *(const u32*)&sQ[(r0 + 8) * ASTR + ks + 2 * t + 8];
            u32 bh2[8][2], bl2[8][2];
#pragma unroll
            for (int an = 0; an < 8; an++) {
                const int n = an * 8 + g;
                bh2[an][0] = *(const u32*)&sKh[n * ASTR + ks + 2 * t];
                bh2[an][1] = *(const u32*)&sKh[n * ASTR + ks + 2 * t + 8];
                bl2[an][0] = *(const u32*)&sKl[n * ASTR + ks + 2 * t];
                bl2[an][1] = *(const u32*)&sKl[n * ASTR + ks + 2 * t + 8];
            }
#pragma unroll
            for (int an = 0; an < 8; an++) MMA_F16(sacc[an], aq, bh2[an]);
#pragma unroll
            for (int an = 0; an < 8; an++) MMA_F16(sacc[an], aq, bl2[an]);
        }

        const int qr0 = qBase + wrow + g;
        const int qr1 = qr0 + 8;
#pragma unroll
        for (int an = 0; an < 8; an++) {
            const int c0 = kBase + an * 8 + 2 * t;
            sacc[an][0] = (c0     <= qr0) ? sacc[an][0] * sl2e : -1e30f;
            sacc[an][1] = (c0 + 1 <= qr0) ? sacc[an][1] * sl2e : -1e30f;
            sacc[an][2] = (c0     <= qr1) ? sacc[an][2] * sl2e : -1e30f;
            sacc[an][3] = (c0 + 1 <= qr1) ? sacc[an][3] * sl2e : -1e30f;
        }

        float mx0 = -1e30f, mx1 = -1e30f;
#pragma unroll
        for (int an = 0; an < 8; an++) {
            mx0 = fmaxf(mx0, fmaxf(sacc[an][0], sacc[an][1]));
            mx1 = fmaxf(mx1, fmaxf(sacc[an][2], sacc[an][3]));
        }
        mx0 = fmaxf(mx0, __shfl_xor_sync(0xffffffffu, mx0, 1));
        mx0 = fmaxf(mx0, __shfl_xor_sync(0xffffffffu, mx0, 2));
        mx1 = fmaxf(mx1, __shfl_xor_sync(0xffffffffu, mx1, 1));
        mx1 = fmaxf(mx1, __shfl_xor_sync(0xffffffffu, mx1, 2));

        const float mn0 = fmaxf(m0, mx0), mn1 = fmaxf(m1, mx1);
        const float al0 = ex2f(m0 - mn0), al1 = ex2f(m1 - mn1);
        m0 = mn0; m1 = mn1;

        float s0 = 0.f, s1 = 0.f;
#pragma unroll
        for (int an = 0; an < 8; an++) {
            sacc[an][0] = ex2f(sacc[an][0] - mn0);
            sacc[an][1] = ex2f(sacc[an][1] - mn0);
            sacc[an][2] = ex2f(sacc[an][2] - mn1);
            sacc[an][3] = ex2f(sacc[an][3] - mn1);
            s0 += sacc[an][0] + sacc[an][1];
            s1 += sacc[an][2] + sacc[an][3];
        }
        s0 += __shfl_xor_sync(0xffffffffu, s0, 1);
        s0 += __shfl_xor_sync(0xffffffffu, s0, 2);
        s1 += __shfl_xor_sync(0xffffffffu, s1, 1);
        s1 += __shfl_xor_sync(0xffffffffu, s1, 2);
        l0 = l0 * al0 + s0;
        l1 = l1 * al1 + s1;

#pragma unroll
        for (int j = 0; j < 16; j++) {
            o[j][0] *= al0; o[j][1] *= al0;
            o[j][2] *= al1; o[j][3] *= al1;
        }

        const u16* sV16 = (const u16*)sV;
#pragma unroll
        for (int jp = 0; jp < 4; jp++) {
            u32 ap[4];
            ap[0] = pack2h(sacc[2 * jp][0],     sacc[2 * jp][1]);
            ap[1] = pack2h(sacc[2 * jp][2],     sacc[2 * jp][3]);
            ap[2] = pack2h(sacc[2 * jp + 1][0], sacc[2 * jp + 1][1]);
            ap[3] = pack2h(sacc[2 * jp + 1][2], sacc[2 * jp + 1][3]);
            const int ks = 16 * jp;
#pragma unroll
            for (int anp = 0; anp < 2; anp++) {
                u32 vb[8][2];
#pragma unroll
                for (int aj = 0; aj < 8; aj++) {
                    const int n = (anp * 8 + aj) * 8 + g;
                    u32 v0 = sV16[(ks + 2 * t)     * ASTR + n];
                    u32 v1 = sV16[(ks + 2 * t + 1) * ASTR + n];
                    u32 v8 = sV16[(ks + 2 * t + 8) * ASTR + n];
                    u32 v9 = sV16[(ks + 2 * t + 9) * ASTR + n];
                    vb[aj][0] = v0 | (v1 << 16);
                    vb[aj][1] = v8 | (v9 << 16);
                }
#pragma unroll
                for (int aj = 0; aj < 8; aj++) MMA_F16(o[anp * 8 + aj], ap, vb[aj]);
            }
        }
    }

    // epilogue: z = O / l -> fp16 single
    const float inv0 = 1.f / l0;
    const float inv1 = 1.f / l1;
    const int r0 = qBase + wrow + g;
#pragma unroll
    for (int an = 0; an < 16; an++) {
        const int col = an * 8 + 2 * t;
#pragma unroll
        for (int half = 0; half < 2; half++) {
            const int row = r0 + 8 * half;
            const float inv = half ? inv1 : inv0;
            float z0 = o[an][2 * half + 0] * inv;
            float z1 = o[an][2 * half + 1] * inv;
            __half2 zp; zp.x = __float2half(z0); zp.y = __float2half(z1);
            const size_t dst = ((size_t)(b * SEQLEN + row) * DMODEL + h * DHEAD + col);
            *(__half2*)&gz16[dst] = zp;
        }
    }
}

// ---------------------------------------------------------------------------
// Launch
// ---------------------------------------------------------------------------
extern "C" void kernel_launch(void* const* d_in, const int* in_sizes, int n_in,
                              void* d_out, int out_size)
{
    const float* x  = (const float*)d_in[0];
    const float* Wq = (const float*)d_in[1];
    const float* Wk = (const float*)d_in[2];
    const float* Wv = (const float*)d_in[3];
    const float* Wo = (const float*)d_in[4];
    const float* bQ = (const float*)d_in[5];
    const float* bK = (const float*)d_in[6];
    const float* bV = (const float*)d_in[7];
    const float* bO = (const float*)d_in[8];
    float* out = (float*)d_out;

    static bool attr_set = false;
    if (!attr_set) {
        cudaFuncSetAttribute(proj_single_kernel, cudaFuncAttributeMaxDynamicSharedMemorySize, GEMM_SMEM);
        cudaFuncSetAttribute(proj_k_kernel, cudaFuncAttributeMaxDynamicSharedMemorySize, GEMM_SMEM);
        cudaFuncSetAttribute(out_mma_kernel, cudaFuncAttributeMaxDynamicSharedMemorySize, GEMM_SMEM);
        cudaFuncSetAttribute(attn_mma_kernel, cudaFuncAttributeMaxDynamicSharedMemorySize, ATTN_SMEM);
        attr_set = true;
    }

    // 0) splits (x -> fp16; weights -> fp16 hi/lo)
    split_x_kernel<<<(MTOT * DMODEL / 2) / 256, 256>>>(x);
    split_w_kernel<<<dim3(DMODEL / 32, DHEAD / 32, 3 * NHEADS), dim3(32, 8)>>>(Wq, Wk, Wv);
    split_wo_kernel<<<dim3(DMODEL / 32, DMODEL / 32), dim3(32, 8)>>>(Wo);

    // 1) projections (fp16 2-term; non-divergent epilogues)
    proj_single_kernel<<<dim3(MTOT / 128, NHEADS, 2), 256, GEMM_SMEM>>>(bQ, bV);
    proj_k_kernel<<<dim3(MTOT / 128, NHEADS), 256, GEMM_SMEM>>>(bK);

    // 2) fp16 flash attention (K 2-term, V single)
    attn_mma_kernel<<<dim3(SEQLEN / 128, NHEADS, BATCH), 256, ATTN_SMEM>>>();

    // 3) output projection (fp16 2-term)
    out_mma_kernel<<<dim3(MTOT / 128, DMODEL / 128), 256, GEMM_SMEM>>>(bO, out);

    (void)in_sizes; (void)n_in; (void)out_size;
}